// round 2
// baseline (speedup 1.0000x reference)
#include <cuda_runtime.h>
#include <math.h>

// Problem constants
#define BB    8
#define CC    256
#define HH    56
#define WW    56
#define HIN   58
#define WIN   58
#define GG    8
#define GCH   32
#define PP    9
#define MTOT  25088      // B*H*W = 8*3136
#define NOFF  144
#define NMSK  72
#define NOM   216

// Scratch (device globals; no runtime allocation allowed)
__device__ float g_vp[BB*HIN*WIN*CC];   // padded projected features, NHWC
__device__ float g_f [MTOT*CC];         // dwconv -> LN -> GELU features, NHWC
__device__ float g_om[MTOT*NOM];        // [offset(144) | mask_logits(72)] per position
__device__ float g_s [MTOT*CC];         // sampled/aggregated features, NHWC

// ---------------------------------------------------------------------------
// Zero the padded feature buffer (borders must be 0; interior overwritten).
// ---------------------------------------------------------------------------
__global__ void zero_vp_kernel() {
    const int n4 = (BB*HIN*WIN*CC) / 4;
    float4* p = reinterpret_cast<float4*>(g_vp);
    for (int i = blockIdx.x * blockDim.x + threadIdx.x; i < n4;
         i += gridDim.x * blockDim.x) {
        p[i] = make_float4(0.f, 0.f, 0.f, 0.f);
    }
}

// ---------------------------------------------------------------------------
// Generic tiled SGEMM, M=25088, K=256.
// MODE 0: A = x (NCHW gather), B = w_in, +b_in, write g_vp interior (NHWC pad)
// MODE 1: A = g_f, B = [w_off | w_mask], +[b_off|b_mask], write g_om (N=216)
// MODE 2: A = g_s, B = w_out, +b_out, then BN + SiLU, write d_out (NCHW)
// Tiles: BM=128, BN=64, BK=16, 256 threads, 8x4 per-thread microtile.
// ---------------------------------------------------------------------------
template<int MODE>
__global__ __launch_bounds__(256)
void sgemm_kernel(const float* __restrict__ Xptr,
                  const float* __restrict__ Bp,
                  const float* __restrict__ B2p,
                  const float* __restrict__ bias,
                  const float* __restrict__ bias2,
                  float* __restrict__ Cout,
                  const float* __restrict__ bn_g,
                  const float* __restrict__ bn_b,
                  const float* __restrict__ bn_mean,
                  const float* __restrict__ bn_var)
{
    __shared__ float As[16][132];   // [k][m], padded stride for bank spread
    __shared__ float Bs[16][64];    // [k][n]

    const int tid = threadIdx.x;
    const int tx  = tid & 15;       // 0..15 -> n
    const int ty  = tid >> 4;       // 0..15 -> m
    const int m0  = blockIdx.y * 128;
    const int n0  = blockIdx.x * 64;

    float acc[8][4];
#pragma unroll
    for (int i = 0; i < 8; i++)
#pragma unroll
        for (int j = 0; j < 4; j++) acc[i][j] = 0.f;

    const float* Adir = (MODE == 1) ? g_f : g_s;

    for (int kt = 0; kt < 256; kt += 16) {
        // ---- load A tile ----
        if (MODE == 0) {
            // gather from x NCHW: A[m,k] = x[(b*256+k)*3136 + hw]
#pragma unroll
            for (int t = 0; t < 8; t++) {
                int idx = t * 256 + tid;
                int m_l = idx & 127;
                int k_l = idx >> 7;
                int m   = m0 + m_l;
                int b   = m / 3136;
                int hw  = m - b * 3136;
                As[k_l][m_l] = Xptr[((size_t)(b * 256 + kt + k_l)) * 3136 + hw];
            }
        } else {
            // direct row-major [M,256]
            int m_l = tid >> 1;
            int kh  = (tid & 1) * 8;
            const float* src = Adir + (size_t)(m0 + m_l) * 256 + kt + kh;
            float4 v0 = *(const float4*)(src);
            float4 v1 = *(const float4*)(src + 4);
            As[kh + 0][m_l] = v0.x; As[kh + 1][m_l] = v0.y;
            As[kh + 2][m_l] = v0.z; As[kh + 3][m_l] = v0.w;
            As[kh + 4][m_l] = v1.x; As[kh + 5][m_l] = v1.y;
            As[kh + 6][m_l] = v1.z; As[kh + 7][m_l] = v1.w;
        }
        // ---- load B tile ----
#pragma unroll
        for (int t = 0; t < 4; t++) {
            int idx = t * 256 + tid;
            int n_l = idx & 63;
            int k_l = idx >> 6;
            int n   = n0 + n_l;
            int k   = kt + k_l;
            float v;
            if (MODE == 1) {
                if (n < NOFF)       v = Bp[k * NOFF + n];
                else if (n < NOM)   v = B2p[k * NMSK + (n - NOFF)];
                else                v = 0.f;
            } else {
                v = Bp[k * 256 + n];
            }
            Bs[k_l][n_l] = v;
        }
        __syncthreads();

        // ---- compute ----
#pragma unroll
        for (int k = 0; k < 16; k++) {
            float a[8], bv[4];
            float4 a0 = *(const float4*)&As[k][ty * 8];
            float4 a1 = *(const float4*)&As[k][ty * 8 + 4];
            a[0] = a0.x; a[1] = a0.y; a[2] = a0.z; a[3] = a0.w;
            a[4] = a1.x; a[5] = a1.y; a[6] = a1.z; a[7] = a1.w;
            float4 b0 = *(const float4*)&Bs[k][tx * 4];
            bv[0] = b0.x; bv[1] = b0.y; bv[2] = b0.z; bv[3] = b0.w;
#pragma unroll
            for (int i = 0; i < 8; i++)
#pragma unroll
                for (int j = 0; j < 4; j++)
                    acc[i][j] = fmaf(a[i], bv[j], acc[i][j]);
        }
        __syncthreads();
    }

    // ---- epilogue ----
#pragma unroll
    for (int i = 0; i < 8; i++) {
        int m  = m0 + ty * 8 + i;
        int b  = m / 3136;
        int hw = m - b * 3136;
#pragma unroll
        for (int j = 0; j < 4; j++) {
            int n = n0 + tx * 4 + j;
            float val = acc[i][j];
            if (MODE == 0) {
                val += bias[n];
                int h = hw / 56;
                int w = hw - h * 56;
                g_vp[(((size_t)(b * 58 + h + 1)) * 58 + (w + 1)) * 256 + n] = val;
            } else if (MODE == 1) {
                if (n < NOM) {
                    val += (n < NOFF) ? bias[n] : bias2[n - NOFF];
                    g_om[(size_t)m * NOM + n] = val;
                }
            } else {
                val += bias[n];
                float sc = bn_g[n] * rsqrtf(bn_var[n] + 1e-5f);
                float t  = (val - bn_mean[n]) * sc + bn_b[n];
                float o  = t / (1.f + expf(-t));          // SiLU
                Cout[((size_t)(b * 256 + n)) * 3136 + hw] = o;
            }
        }
    }
}

// ---------------------------------------------------------------------------
// Depthwise 3x3 conv (NCHW in) -> write NHWC to g_f (pre-LN).
// grid: (C/32, H, B), 256 threads. Smem tile: 32 ch x 3 rows x 58 cols.
// ---------------------------------------------------------------------------
__global__ __launch_bounds__(256)
void dwconv_kernel(const float* __restrict__ x,
                   const float* __restrict__ dw_w,
                   const float* __restrict__ dw_b)
{
    __shared__ float sx[32 * 177];   // [c]*177 + r*59 + col  (conflict-free strides)
    __shared__ float sw[32 * 9];
    __shared__ float sb[32];

    const int c0  = blockIdx.x * 32;
    const int h   = blockIdx.y;
    const int b   = blockIdx.z;
    const int tid = threadIdx.x;

    // FIX (R1 bug): 288 weights but 256 threads -> must stride the load.
    for (int i = tid; i < 288; i += 256) sw[i] = dw_w[c0 * 9 + i];
    if (tid < 32)  sb[tid] = dw_b[c0 + tid];

    for (int idx = tid; idx < 32 * 3 * 58; idx += 256) {
        int col = idx % 58;
        int r   = (idx / 58) % 3;
        int c   = idx / 174;
        int hh  = h - 1 + r;
        int wwc = col - 1;
        float v = 0.f;
        if (hh >= 0 && hh < 56 && wwc >= 0 && wwc < 56)
            v = x[((size_t)(b * 256 + c0 + c)) * 3136 + hh * 56 + wwc];
        sx[c * 177 + r * 59 + col] = v;
    }
    __syncthreads();

    for (int oi = tid; oi < 32 * 56; oi += 256) {
        int c = oi & 31;
        int w = oi >> 5;
        float accv = sb[c];
#pragma unroll
        for (int r = 0; r < 3; r++)
#pragma unroll
            for (int j = 0; j < 3; j++)
                accv = fmaf(sx[c * 177 + r * 59 + w + j], sw[c * 9 + r * 3 + j], accv);
        g_f[((size_t)((b * 56 + h) * 56 + w)) * 256 + c0 + c] = accv;
    }
}

// ---------------------------------------------------------------------------
// LayerNorm (over C=256) + exact GELU, in place on g_f. One block per position.
// ---------------------------------------------------------------------------
__global__ __launch_bounds__(256)
void ln_gelu_kernel(const float* __restrict__ ln_g,
                    const float* __restrict__ ln_b)
{
    const int m = blockIdx.x;
    const int c = threadIdx.x;
    float v = g_f[(size_t)m * 256 + c];

    float s = v, s2 = v * v;
#pragma unroll
    for (int o = 16; o; o >>= 1) {
        s  += __shfl_xor_sync(0xffffffffu, s,  o);
        s2 += __shfl_xor_sync(0xffffffffu, s2, o);
    }
    __shared__ float ws[8], ws2[8];
    const int warp = c >> 5, lane = c & 31;
    if (lane == 0) { ws[warp] = s; ws2[warp] = s2; }
    __syncthreads();
    if (warp == 0) {
        float a  = (lane < 8) ? ws[lane]  : 0.f;
        float a2 = (lane < 8) ? ws2[lane] : 0.f;
#pragma unroll
        for (int o = 4; o; o >>= 1) {
            a  += __shfl_xor_sync(0xffffffffu, a,  o);
            a2 += __shfl_xor_sync(0xffffffffu, a2, o);
        }
        if (lane == 0) { ws[0] = a; ws2[0] = a2; }
    }
    __syncthreads();

    float mean = ws[0]  * (1.f / 256.f);
    float var  = ws2[0] * (1.f / 256.f) - mean * mean;
    float xn   = (v - mean) * rsqrtf(var + 1e-5f) * ln_g[c] + ln_b[c];
    float ge   = 0.5f * xn * (1.f + erff(xn * 0.70710678118654752f));
    g_f[(size_t)m * 256 + c] = ge;
}

// ---------------------------------------------------------------------------
// Deformable sampling. One block per position; warp g handles group g,
// lane = channel within group. px = w + p/3 + off_x ; py = h + p%3 + off_y.
// ---------------------------------------------------------------------------
__global__ __launch_bounds__(256)
void sample_kernel()
{
    const int m    = blockIdx.x;
    const int b    = m / 3136;
    const int hw   = m - b * 3136;
    const int h    = hw / 56;
    const int w    = hw - h * 56;
    const int g    = threadIdx.x >> 5;
    const int lane = threadIdx.x & 31;

    const float* row = g_om + (size_t)m * 216;

    float offx[9], offy[9], mk[9];
    float mx = -3.0e38f;
#pragma unroll
    for (int p = 0; p < 9; p++) {
        offx[p] = row[g * 18 + 2 * p];
        offy[p] = row[g * 18 + 2 * p + 1];
        mk[p]   = row[144 + g * 9 + p];
        mx = fmaxf(mx, mk[p]);
    }
    float sum = 0.f;
#pragma unroll
    for (int p = 0; p < 9; p++) { mk[p] = expf(mk[p] - mx); sum += mk[p]; }
    const float inv = 1.f / sum;

    float acc = 0.f;
    const float* vpg = g_vp + (size_t)b * 58 * 58 * 256 + g * 32 + lane;

#pragma unroll
    for (int p = 0; p < 9; p++) {
        float px = (float)(w + (p / 3)) + offx[p];
        float py = (float)(h + (p % 3)) + offy[p];
        float x0f = floorf(px), y0f = floorf(py);
        float wx = px - x0f, wy = py - y0f;
        int x0 = (int)x0f, y0 = (int)y0f;
        int x1 = x0 + 1,   y1 = y0 + 1;
        float vx0 = (x0 >= 0 && x0 < 58) ? 1.f : 0.f;
        float vx1 = (x1 >= 0 && x1 < 58) ? 1.f : 0.f;
        float vy0 = (y0 >= 0 && y0 < 58) ? 1.f : 0.f;
        float vy1 = (y1 >= 0 && y1 < 58) ? 1.f : 0.f;
        int x0c = min(max(x0, 0), 57), x1c = min(max(x1, 0), 57);
        int y0c = min(max(y0, 0), 57), y1c = min(max(y1, 0), 57);

        float mp  = mk[p] * inv;
        float w00 = (1.f - wx) * (1.f - wy) * vx0 * vy0 * mp;
        float w01 = wx * (1.f - wy) * vx1 * vy0 * mp;
        float w10 = (1.f - wx) * wy * vx0 * vy1 * mp;
        float w11 = wx * wy * vx1 * vy1 * mp;

        acc += w00 * vpg[(y0c * 58 + x0c) * 256]
             + w01 * vpg[(y0c * 58 + x1c) * 256]
             + w10 * vpg[(y1c * 58 + x0c) * 256]
             + w11 * vpg[(y1c * 58 + x1c) * 256];
    }
    g_s[(size_t)m * 256 + g * 32 + lane] = acc;
}

// ---------------------------------------------------------------------------
extern "C" void kernel_launch(void* const* d_in, const int* in_sizes, int n_in,
                              void* d_out, int out_size)
{
    const float* x      = (const float*)d_in[0];
    const float* w_in   = (const float*)d_in[1];
    const float* b_in   = (const float*)d_in[2];
    const float* dw_w   = (const float*)d_in[3];
    const float* dw_b   = (const float*)d_in[4];
    const float* ln_g   = (const float*)d_in[5];
    const float* ln_b   = (const float*)d_in[6];
    const float* w_off  = (const float*)d_in[7];
    const float* b_off  = (const float*)d_in[8];
    const float* w_mask = (const float*)d_in[9];
    const float* b_mask = (const float*)d_in[10];
    const float* w_out  = (const float*)d_in[11];
    const float* b_out  = (const float*)d_in[12];
    const float* bn_g   = (const float*)d_in[13];
    const float* bn_b   = (const float*)d_in[14];
    const float* bn_mean= (const float*)d_in[15];
    const float* bn_var = (const float*)d_in[16];
    float* out = (float*)d_out;

    dim3 ggrid(4, 196);

    zero_vp_kernel<<<1024, 256>>>();
    // input projection -> padded vp (NHWC)
    sgemm_kernel<0><<<ggrid, 256>>>(x, w_in, nullptr, b_in, nullptr, nullptr,
                                    nullptr, nullptr, nullptr, nullptr);
    // offset/mask branch features
    dwconv_kernel<<<dim3(8, 56, 8), 256>>>(x, dw_w, dw_b);
    ln_gelu_kernel<<<25088, 256>>>(ln_g, ln_b);
    // offset + mask projection (concat GEMM, N=216)
    sgemm_kernel<1><<<ggrid, 256>>>(nullptr, w_off, w_mask, b_off, b_mask, nullptr,
                                    nullptr, nullptr, nullptr, nullptr);
    // deformable bilinear sampling + mask aggregation
    sample_kernel<<<25088, 256>>>();
    // output projection + BN + SiLU -> NCHW
    sgemm_kernel<2><<<ggrid, 256>>>(nullptr, w_out, nullptr, b_out, nullptr, out,
                                    bn_g, bn_b, bn_mean, bn_var);
}

// round 4
// speedup vs baseline: 1.3614x; 1.3614x over previous
#include <cuda_runtime.h>
#include <cuda_bf16.h>
#include <math.h>
#include <stdint.h>

// Problem constants
#define BB    8
#define CC    256
#define HH    56
#define WW    56
#define HIN   58
#define WIN   58
#define MTOT  25088      // B*H*W
#define NOFF  144
#define NMSK  72
#define NOM   216

// Scratch (device globals; no runtime allocation allowed)
__device__ float g_vp[BB*HIN*WIN*CC];        // padded projected features, NHWC fp32
__device__ float g_f [MTOT*CC];              // dwconv output (pre-LN), NHWC fp32
__device__ float g_om[MTOT*NOM];             // [offset(144) | mask(72)] logits
__device__ __nv_bfloat16 g_ah[MTOT*CC];      // activation bf16 hi   [m][k]
__device__ __nv_bfloat16 g_al[MTOT*CC];      // activation bf16 lo   [m][k]
__device__ __nv_bfloat16 g_wth[3*65536];     // weights^T [which][n][k], hi
__device__ __nv_bfloat16 g_wtl[3*65536];     // weights^T lo

// ---------------------------------------------------------------------------
// fp32 -> bf16 hi/lo split helpers
// ---------------------------------------------------------------------------
__device__ __forceinline__ uint32_t hibits(float v) {
    uint32_t u = __float_as_uint(v);
    return (u + 0x7FFFu + ((u >> 16) & 1u)) & 0xFFFF0000u;
}
__device__ __forceinline__ uint32_t hi2(float a, float b) {
    return (hibits(a) >> 16) | (hibits(b) & 0xFFFF0000u);
}
__device__ __forceinline__ uint32_t lo2(float a, float b) {
    float la = a - __uint_as_float(hibits(a));
    float lb = b - __uint_as_float(hibits(b));
    uint32_t r;
    asm("cvt.rn.satfinite.bf16x2.f32 %0, %1, %2;" : "=r"(r) : "f"(lb), "f"(la));
    return r;   // low half = la (k even), high half = lb (k odd)
}
__device__ __forceinline__ void split1(float v, __nv_bfloat16* ph, __nv_bfloat16* pl) {
    uint32_t hb = hibits(v);
    __nv_bfloat16_raw hr; hr.x = (unsigned short)(hb >> 16);
    *ph = __nv_bfloat16(hr);
    *pl = __float2bfloat16(v - __uint_as_float(hb));
}

// mma.sync m16n8k16 bf16 -> f32 (portable tensor-core path; compute_103-safe)
__device__ __forceinline__ void mma16816(float* c, const uint32_t* a, const uint32_t* b) {
    asm volatile(
        "mma.sync.aligned.m16n8k16.row.col.f32.bf16.bf16.f32 "
        "{%0,%1,%2,%3}, {%4,%5,%6,%7}, {%8,%9}, {%0,%1,%2,%3};"
        : "+f"(c[0]), "+f"(c[1]), "+f"(c[2]), "+f"(c[3])
        : "r"(a[0]), "r"(a[1]), "r"(a[2]), "r"(a[3]), "r"(b[0]), "r"(b[1]));
}

// ---------------------------------------------------------------------------
// Weight prep: transpose + bf16 hi/lo split.  idx = which*65536 + n*256 + k
// (mode-1 weights zero-padded from 216 to 256 columns)
// ---------------------------------------------------------------------------
__global__ void prep_weights(const float* __restrict__ w_in,
                             const float* __restrict__ w_off,
                             const float* __restrict__ w_mask,
                             const float* __restrict__ w_out)
{
    int idx = blockIdx.x * 256 + threadIdx.x;
    int which = idx >> 16;
    int n = (idx >> 8) & 255;
    int k = idx & 255;
    float v;
    if (which == 0)      v = w_in[k * 256 + n];
    else if (which == 1) v = (n < NOFF) ? w_off[k * NOFF + n]
                           : (n < NOM) ? w_mask[k * NMSK + (n - NOFF)] : 0.f;
    else                 v = w_out[k * 256 + n];
    split1(v, &g_wth[idx], &g_wtl[idx]);
}

// ---------------------------------------------------------------------------
// x (NCHW) -> g_ah/g_al [m][k] via smem transpose.  grid = 784 (32 m per block)
// 3136 % 32 == 0 so blocks never straddle a batch boundary.
// ---------------------------------------------------------------------------
__global__ __launch_bounds__(256)
void prep_x(const float* __restrict__ x)
{
    __shared__ float s[32][257];
    const int mb = blockIdx.x * 32;
    const int b = mb / 3136, hw0 = mb % 3136;
    const int lane = threadIdx.x & 31, kw = threadIdx.x >> 5;
#pragma unroll
    for (int p = 0; p < 32; p++) {
        int k = p * 8 + kw;
        s[lane][k] = x[((size_t)(b * 256 + k)) * 3136 + hw0 + lane];
    }
    __syncthreads();
    const int row = threadIdx.x >> 3, seg = threadIdx.x & 7;
    const int m = mb + row, k0 = seg * 32;
    uint32_t hi[16], lo[16];
#pragma unroll
    for (int j = 0; j < 16; j++) {
        float a = s[row][k0 + 2 * j], bv = s[row][k0 + 2 * j + 1];
        hi[j] = hi2(a, bv); lo[j] = lo2(a, bv);
    }
    uint4* dh = (uint4*)(g_ah + (size_t)m * 256 + k0);
    uint4* dl = (uint4*)(g_al + (size_t)m * 256 + k0);
#pragma unroll
    for (int q = 0; q < 4; q++) {
        dh[q] = make_uint4(hi[4*q], hi[4*q+1], hi[4*q+2], hi[4*q+3]);
        dl[q] = make_uint4(lo[4*q], lo[4*q+1], lo[4*q+2], lo[4*q+3]);
    }
}

// ---------------------------------------------------------------------------
__global__ void zero_vp_kernel() {
    const int n4 = (BB*HIN*WIN*CC) / 4;
    float4* p = reinterpret_cast<float4*>(g_vp);
    for (int i = blockIdx.x * blockDim.x + threadIdx.x; i < n4;
         i += gridDim.x * blockDim.x)
        p[i] = make_float4(0.f, 0.f, 0.f, 0.f);
}

// ---------------------------------------------------------------------------
// Tensor-core GEMM via mma.sync, bf16 3-term split, fp32 accum.
// C[m][n] = act[m][k] * W^T[n][k].  Block tile 128m x 128n, K=256 in 4 chunks.
// Roles swapped: W rows feed the mma A-operand (row-major), act rows feed the
// B-operand (col-major k x m) -- both are k-contiguous loads.
// MODE 0: -> g_vp interior (NHWC pad, +b_in)
// MODE 1: -> g_om (216 cols, +b_off/b_mask)
// MODE 2: -> d_out NCHW with folded BN + SiLU
// ---------------------------------------------------------------------------
#define SMEM_GEMM 73728   // 4 tensors * 128 rows * 72 bf16 (144B row stride)

template<int MODE>
__global__ __launch_bounds__(256, 1)
void gemm_mma(const float* __restrict__ bias,
              const float* __restrict__ bias2,
              float* __restrict__ Cout,
              const float* __restrict__ bn_g, const float* __restrict__ bn_b,
              const float* __restrict__ bn_mean, const float* __restrict__ bn_var)
{
    extern __shared__ char smem[];
    char* sWh = smem;
    char* sWl = smem + 18432;
    char* sMh = smem + 36864;
    char* sMl = smem + 55296;

    const int tid = threadIdx.x, wid = tid >> 5, lane = tid & 31;
    const int g = lane >> 2, tig = lane & 3;
    const int nb0 = blockIdx.x * 128, mb0 = blockIdx.y * 128;
    const int nw4 = wid & 3;    // n-slab (32 rows of W)
    const int mw2 = wid >> 2;   // m-slab (64 act rows)

    const __nv_bfloat16* wth = g_wth + MODE * 65536;
    const __nv_bfloat16* wtl = g_wtl + MODE * 65536;

    float acc[2][8][4];
#pragma unroll
    for (int a = 0; a < 2; a++)
#pragma unroll
        for (int b = 0; b < 8; b++)
#pragma unroll
            for (int c = 0; c < 4; c++) acc[a][b][c] = 0.f;

    for (int chv = 0; chv < 4; chv++) {
        const int k0c = chv * 64;
#pragma unroll
        for (int i = 0; i < 4; i++) {
            int idx = i * 256 + tid;
            int r = idx >> 3, seg = idx & 7;
            uint32_t so = (uint32_t)(r * 144 + seg * 16);
            size_t wof = (size_t)(nb0 + r) * 256 + k0c + seg * 8;
            size_t mof = (size_t)(mb0 + r) * 256 + k0c + seg * 8;
            *(uint4*)(sWh + so) = *(const uint4*)(wth + wof);
            *(uint4*)(sWl + so) = *(const uint4*)(wtl + wof);
            *(uint4*)(sMh + so) = *(const uint4*)(g_ah + mof);
            *(uint4*)(sMl + so) = *(const uint4*)(g_al + mof);
        }
        __syncthreads();

#pragma unroll
        for (int ks = 0; ks < 4; ks++) {
            const int kk = ks * 16 + tig * 2;
            uint32_t wh[2][4], wl[2][4], mh[8][2], ml[8][2];
#pragma unroll
            for (int mt = 0; mt < 2; mt++) {
                int r = nw4 * 32 + mt * 16 + g;
                uint32_t o0 = (uint32_t)(r * 144 + kk * 2);
                uint32_t o1 = (uint32_t)((r + 8) * 144 + kk * 2);
                wh[mt][0] = *(uint32_t*)(sWh + o0);
                wh[mt][1] = *(uint32_t*)(sWh + o1);
                wh[mt][2] = *(uint32_t*)(sWh + o0 + 16);
                wh[mt][3] = *(uint32_t*)(sWh + o1 + 16);
                wl[mt][0] = *(uint32_t*)(sWl + o0);
                wl[mt][1] = *(uint32_t*)(sWl + o1);
                wl[mt][2] = *(uint32_t*)(sWl + o0 + 16);
                wl[mt][3] = *(uint32_t*)(sWl + o1 + 16);
            }
#pragma unroll
            for (int nt = 0; nt < 8; nt++) {
                int r = mw2 * 64 + nt * 8 + g;
                uint32_t o = (uint32_t)(r * 144 + kk * 2);
                mh[nt][0] = *(uint32_t*)(sMh + o);
                mh[nt][1] = *(uint32_t*)(sMh + o + 16);
                ml[nt][0] = *(uint32_t*)(sMl + o);
                ml[nt][1] = *(uint32_t*)(sMl + o + 16);
            }
#pragma unroll
            for (int mt = 0; mt < 2; mt++)
#pragma unroll
                for (int nt = 0; nt < 8; nt++)
                    mma16816(acc[mt][nt], wh[mt], mh[nt]);
#pragma unroll
            for (int mt = 0; mt < 2; mt++)
#pragma unroll
                for (int nt = 0; nt < 8; nt++)
                    mma16816(acc[mt][nt], wh[mt], ml[nt]);
#pragma unroll
            for (int mt = 0; mt < 2; mt++)
#pragma unroll
                for (int nt = 0; nt < 8; nt++)
                    mma16816(acc[mt][nt], wl[mt], mh[nt]);
        }
        __syncthreads();
    }

    // ---- stage C tile to smem [m_loc][n_loc], stride 129 (conflict-free cols)
    float* sOut = (float*)smem;
#pragma unroll
    for (int mt = 0; mt < 2; mt++)
#pragma unroll
        for (int nt = 0; nt < 8; nt++) {
            int n_loc = nw4 * 32 + mt * 16 + g;
            int m_loc = mw2 * 64 + nt * 8 + tig * 2;
            sOut[m_loc * 129 + n_loc]            = acc[mt][nt][0];
            sOut[(m_loc + 1) * 129 + n_loc]      = acc[mt][nt][1];
            sOut[m_loc * 129 + n_loc + 8]        = acc[mt][nt][2];
            sOut[(m_loc + 1) * 129 + n_loc + 8]  = acc[mt][nt][3];
        }
    __syncthreads();

    // ---- mode-specific global stores ----
    if (MODE == 0) {
        for (int t = tid; t < 128 * 32; t += 256) {
            int m_loc = t >> 5, c4 = (t & 31) * 4;
            int m = mb0 + m_loc;
            int b = m / 3136, hw = m - b * 3136;
            int h = hw / 56, w = hw - h * 56;
            float4 v;
            v.x = sOut[m_loc * 129 + c4 + 0] + __ldg(&bias[nb0 + c4 + 0]);
            v.y = sOut[m_loc * 129 + c4 + 1] + __ldg(&bias[nb0 + c4 + 1]);
            v.z = sOut[m_loc * 129 + c4 + 2] + __ldg(&bias[nb0 + c4 + 2]);
            v.w = sOut[m_loc * 129 + c4 + 3] + __ldg(&bias[nb0 + c4 + 3]);
            *(float4*)(g_vp + ((size_t)((b * 58 + h + 1) * 58 + (w + 1))) * 256
                       + nb0 + c4) = v;
        }
    } else if (MODE == 1) {
        const int nq = (nb0 == 0) ? 32 : 22;   // float4 cols: 128 or 88 (216-128)
        for (int t = tid; t < 128 * nq; t += 256) {
            int m_loc = t / nq, c4 = (t - m_loc * nq) * 4;
            int n = nb0 + c4;
            float4 v;
            float* sp = &sOut[m_loc * 129 + c4];
            v.x = sp[0] + ((n + 0 < NOFF) ? __ldg(&bias[n + 0]) : __ldg(&bias2[n + 0 - NOFF]));
            v.y = sp[1] + ((n + 1 < NOFF) ? __ldg(&bias[n + 1]) : __ldg(&bias2[n + 1 - NOFF]));
            v.z = sp[2] + ((n + 2 < NOFF) ? __ldg(&bias[n + 2]) : __ldg(&bias2[n + 2 - NOFF]));
            v.w = sp[3] + ((n + 3 < NOFF) ? __ldg(&bias[n + 3]) : __ldg(&bias2[n + 3 - NOFF]));
            *(float4*)(g_om + (size_t)(mb0 + m_loc) * 216 + n) = v;
        }
    } else {
        for (int ni = wid; ni < 128; ni += 8) {
            int n = nb0 + ni;
            float kA = __ldg(&bn_g[n]) * rsqrtf(__ldg(&bn_var[n]) + 1e-5f);
            float kB = (__ldg(&bias[n]) - __ldg(&bn_mean[n])) * kA + __ldg(&bn_b[n]);
#pragma unroll
            for (int mh2 = 0; mh2 < 4; mh2++) {
                int m_loc = mh2 * 32 + lane;
                int m = mb0 + m_loc;
                int b = m / 3136, hw = m - b * 3136;
                float f = sOut[m_loc * 129 + ni] * kA + kB;
                float o = f / (1.f + expf(-f));
                Cout[((size_t)(b * 256 + n)) * 3136 + hw] = o;
            }
        }
    }
}

// ---------------------------------------------------------------------------
// Depthwise 3x3 conv (NCHW in) -> NHWC g_f (pre-LN).
// ---------------------------------------------------------------------------
__global__ __launch_bounds__(256)
void dwconv_kernel(const float* __restrict__ x,
                   const float* __restrict__ dw_w,
                   const float* __restrict__ dw_b)
{
    __shared__ float sx[32 * 177];
    __shared__ float sw_[32 * 9];
    __shared__ float sb_[32];

    const int c0  = blockIdx.x * 32;
    const int h   = blockIdx.y;
    const int b   = blockIdx.z;
    const int tid = threadIdx.x;

    for (int i = tid; i < 288; i += 256) sw_[i] = dw_w[c0 * 9 + i];
    if (tid < 32) sb_[tid] = dw_b[c0 + tid];

    for (int idx = tid; idx < 32 * 3 * 58; idx += 256) {
        int col = idx % 58;
        int r   = (idx / 58) % 3;
        int c   = idx / 174;
        int hh  = h - 1 + r;
        int wwc = col - 1;
        float v = 0.f;
        if (hh >= 0 && hh < 56 && wwc >= 0 && wwc < 56)
            v = x[((size_t)(b * 256 + c0 + c)) * 3136 + hh * 56 + wwc];
        sx[c * 177 + r * 59 + col] = v;
    }
    __syncthreads();

    for (int oi = tid; oi < 32 * 56; oi += 256) {
        int c = oi & 31;
        int w = oi >> 5;
        float accv = sb_[c];
#pragma unroll
        for (int r = 0; r < 3; r++)
#pragma unroll
            for (int j = 0; j < 3; j++)
                accv = fmaf(sx[c * 177 + r * 59 + w + j], sw_[c * 9 + r * 3 + j], accv);
        g_f[((size_t)((b * 56 + h) * 56 + w)) * 256 + c0 + c] = accv;
    }
}

// ---------------------------------------------------------------------------
// LayerNorm (C=256) + exact GELU; reads g_f, writes split bf16 to g_ah/g_al.
// ---------------------------------------------------------------------------
__global__ __launch_bounds__(256)
void ln_gelu_kernel(const float* __restrict__ ln_g,
                    const float* __restrict__ ln_b)
{
    const int m = blockIdx.x;
    const int c = threadIdx.x;
    float v = g_f[(size_t)m * 256 + c];

    float s = v, s2 = v * v;
#pragma unroll
    for (int o = 16; o; o >>= 1) {
        s  += __shfl_xor_sync(0xffffffffu, s,  o);
        s2 += __shfl_xor_sync(0xffffffffu, s2, o);
    }
    __shared__ float ws[8], ws2[8];
    const int warp = c >> 5, lane = c & 31;
    if (lane == 0) { ws[warp] = s; ws2[warp] = s2; }
    __syncthreads();
    if (warp == 0) {
        float a  = (lane < 8) ? ws[lane]  : 0.f;
        float a2 = (lane < 8) ? ws2[lane] : 0.f;
#pragma unroll
        for (int o = 4; o; o >>= 1) {
            a  += __shfl_xor_sync(0xffffffffu, a,  o);
            a2 += __shfl_xor_sync(0xffffffffu, a2, o);
        }
        if (lane == 0) { ws[0] = a; ws2[0] = a2; }
    }
    __syncthreads();

    float mean = ws[0]  * (1.f / 256.f);
    float var  = ws2[0] * (1.f / 256.f) - mean * mean;
    float xn   = (v - mean) * rsqrtf(var + 1e-5f) * ln_g[c] + ln_b[c];
    float ge   = 0.5f * xn * (1.f + erff(xn * 0.70710678118654752f));
    split1(ge, &g_ah[(size_t)m * 256 + c], &g_al[(size_t)m * 256 + c]);
}

// ---------------------------------------------------------------------------
// Deformable sampling; writes split bf16 to g_ah/g_al for the final GEMM.
// ---------------------------------------------------------------------------
__global__ __launch_bounds__(256)
void sample_kernel()
{
    const int m    = blockIdx.x;
    const int b    = m / 3136;
    const int hw   = m - b * 3136;
    const int h    = hw / 56;
    const int w    = hw - h * 56;
    const int g    = threadIdx.x >> 5;
    const int lane = threadIdx.x & 31;

    const float* row = g_om + (size_t)m * 216;

    float offx[9], offy[9], mk[9];
    float mx = -3.0e38f;
#pragma unroll
    for (int p = 0; p < 9; p++) {
        offx[p] = row[g * 18 + 2 * p];
        offy[p] = row[g * 18 + 2 * p + 1];
        mk[p]   = row[144 + g * 9 + p];
        mx = fmaxf(mx, mk[p]);
    }
    float sum = 0.f;
#pragma unroll
    for (int p = 0; p < 9; p++) { mk[p] = expf(mk[p] - mx); sum += mk[p]; }
    const float inv = 1.f / sum;

    float acc = 0.f;
    const float* vpg = g_vp + (size_t)b * 58 * 58 * 256 + g * 32 + lane;

#pragma unroll
    for (int p = 0; p < 9; p++) {
        float px = (float)(w + (p / 3)) + offx[p];
        float py = (float)(h + (p % 3)) + offy[p];
        float x0f = floorf(px), y0f = floorf(py);
        float wx = px - x0f, wy = py - y0f;
        int x0 = (int)x0f, y0 = (int)y0f;
        int x1 = x0 + 1,   y1 = y0 + 1;
        float vx0 = (x0 >= 0 && x0 < 58) ? 1.f : 0.f;
        float vx1 = (x1 >= 0 && x1 < 58) ? 1.f : 0.f;
        float vy0 = (y0 >= 0 && y0 < 58) ? 1.f : 0.f;
        float vy1 = (y1 >= 0 && y1 < 58) ? 1.f : 0.f;
        int x0c = min(max(x0, 0), 57), x1c = min(max(x1, 0), 57);
        int y0c = min(max(y0, 0), 57), y1c = min(max(y1, 0), 57);

        float mp  = mk[p] * inv;
        float w00 = (1.f - wx) * (1.f - wy) * vx0 * vy0 * mp;
        float w01 = wx * (1.f - wy) * vx1 * vy0 * mp;
        float w10 = (1.f - wx) * wy * vx0 * vy1 * mp;
        float w11 = wx * wy * vx1 * vy1 * mp;

        acc += w00 * vpg[(y0c * 58 + x0c) * 256]
             + w01 * vpg[(y0c * 58 + x1c) * 256]
             + w10 * vpg[(y1c * 58 + x0c) * 256]
             + w11 * vpg[(y1c * 58 + x1c) * 256];
    }
    int c = g * 32 + lane;
    split1(acc, &g_ah[(size_t)m * 256 + c], &g_al[(size_t)m * 256 + c]);
}

// ---------------------------------------------------------------------------
extern "C" void kernel_launch(void* const* d_in, const int* in_sizes, int n_in,
                              void* d_out, int out_size)
{
    const float* x      = (const float*)d_in[0];
    const float* b_in   = (const float*)d_in[2];
    const float* dw_w   = (const float*)d_in[3];
    const float* dw_b   = (const float*)d_in[4];
    const float* ln_g   = (const float*)d_in[5];
    const float* ln_b   = (const float*)d_in[6];
    const float* b_off  = (const float*)d_in[8];
    const float* b_mask = (const float*)d_in[10];
    const float* b_out  = (const float*)d_in[12];
    const float* bn_g   = (const float*)d_in[13];
    const float* bn_b   = (const float*)d_in[14];
    const float* bn_mean= (const float*)d_in[15];
    const float* bn_var = (const float*)d_in[16];
    float* out = (float*)d_out;

    cudaFuncSetAttribute(gemm_mma<0>, cudaFuncAttributeMaxDynamicSharedMemorySize, SMEM_GEMM);
    cudaFuncSetAttribute(gemm_mma<1>, cudaFuncAttributeMaxDynamicSharedMemorySize, SMEM_GEMM);
    cudaFuncSetAttribute(gemm_mma<2>, cudaFuncAttributeMaxDynamicSharedMemorySize, SMEM_GEMM);

    dim3 ggrid(2, 196);

    prep_weights<<<768, 256>>>((const float*)d_in[1], (const float*)d_in[7],
                               (const float*)d_in[9], (const float*)d_in[11]);
    prep_x<<<784, 256>>>(x);
    zero_vp_kernel<<<1024, 256>>>();
    // input projection -> padded vp (NHWC)
    gemm_mma<0><<<ggrid, 256, SMEM_GEMM>>>(b_in, nullptr, nullptr,
                                           nullptr, nullptr, nullptr, nullptr);
    // offset/mask branch
    dwconv_kernel<<<dim3(8, 56, 8), 256>>>(x, dw_w, dw_b);
    ln_gelu_kernel<<<25088, 256>>>(ln_g, ln_b);
    gemm_mma<1><<<ggrid, 256, SMEM_GEMM>>>(b_off, b_mask, nullptr,
                                           nullptr, nullptr, nullptr, nullptr);
    // deformable bilinear sampling + mask aggregation
    sample_kernel<<<25088, 256>>>();
    // output projection + BN + SiLU -> NCHW
    gemm_mma<2><<<ggrid, 256, SMEM_GEMM>>>(b_out, nullptr, out,
                                           bn_g, bn_b, bn_mean, bn_var);
}

// round 5
// speedup vs baseline: 1.3821x; 1.0152x over previous
#include <cuda_runtime.h>
#include <cuda_bf16.h>
#include <math.h>
#include <stdint.h>

// Problem constants
#define BB    8
#define CC    256
#define HH    56
#define WW    56
#define HIN   58
#define WIN   58
#define MTOT  25088      // B*H*W
#define NOFF  144
#define NMSK  72
#define NOM   216

// Scratch (device globals; no runtime allocation allowed)
__device__ float g_vp[BB*HIN*WIN*CC];        // padded projected features, NHWC fp32
__device__ float g_f [MTOT*CC];              // dwconv output (pre-LN), NHWC fp32
__device__ float g_om[MTOT*NOM];             // [offset(144) | mask(72)] logits
__device__ __nv_bfloat16 g_ah[MTOT*CC];      // activation bf16 hi   [m][k]
__device__ __nv_bfloat16 g_al[MTOT*CC];      // activation bf16 lo   [m][k]
__device__ __nv_bfloat16 g_wth[3*65536];     // weights^T [which][n][k], hi
__device__ __nv_bfloat16 g_wtl[3*65536];     // weights^T lo

// ---------------------------------------------------------------------------
// fp32 -> bf16 hi/lo split helpers
// ---------------------------------------------------------------------------
__device__ __forceinline__ uint32_t hibits(float v) {
    uint32_t u = __float_as_uint(v);
    return (u + 0x7FFFu + ((u >> 16) & 1u)) & 0xFFFF0000u;
}
__device__ __forceinline__ uint32_t hi2(float a, float b) {
    return (hibits(a) >> 16) | (hibits(b) & 0xFFFF0000u);
}
__device__ __forceinline__ uint32_t lo2(float a, float b) {
    float la = a - __uint_as_float(hibits(a));
    float lb = b - __uint_as_float(hibits(b));
    uint32_t r;
    asm("cvt.rn.satfinite.bf16x2.f32 %0, %1, %2;" : "=r"(r) : "f"(lb), "f"(la));
    return r;   // low half = la (k even), high half = lb (k odd)
}
__device__ __forceinline__ void split1(float v, __nv_bfloat16* ph, __nv_bfloat16* pl) {
    uint32_t hb = hibits(v);
    __nv_bfloat16_raw hr; hr.x = (unsigned short)(hb >> 16);
    *ph = __nv_bfloat16(hr);
    *pl = __float2bfloat16(v - __uint_as_float(hb));
}

// mma.sync m16n8k16 bf16 -> f32 (portable tensor-core path; compute_103-safe)
__device__ __forceinline__ void mma16816(float* c, const uint32_t* a, const uint32_t* b) {
    asm volatile(
        "mma.sync.aligned.m16n8k16.row.col.f32.bf16.bf16.f32 "
        "{%0,%1,%2,%3}, {%4,%5,%6,%7}, {%8,%9}, {%0,%1,%2,%3};"
        : "+f"(c[0]), "+f"(c[1]), "+f"(c[2]), "+f"(c[3])
        : "r"(a[0]), "r"(a[1]), "r"(a[2]), "r"(a[3]), "r"(b[0]), "r"(b[1]));
}

__device__ __forceinline__ uint32_t smem_u32(const void* p) {
    uint32_t a;
    asm("{ .reg .u64 t; cvta.to.shared.u64 t, %1; cvt.u32.u64 %0, t; }"
        : "=r"(a) : "l"(p));
    return a;
}
__device__ __forceinline__ void cpasync16(uint32_t dst, const void* src) {
    asm volatile("cp.async.cg.shared.global [%0], [%1], 16;" :: "r"(dst), "l"(src));
}
#define CP_COMMIT()  asm volatile("cp.async.commit_group;" ::: "memory")
#define CP_WAIT(n)   asm volatile("cp.async.wait_group %0;" :: "n"(n) : "memory")

// ---------------------------------------------------------------------------
// Weight prep: transpose + bf16 hi/lo split.  idx = which*65536 + n*256 + k
// ---------------------------------------------------------------------------
__global__ void prep_weights(const float* __restrict__ w_in,
                             const float* __restrict__ w_off,
                             const float* __restrict__ w_mask,
                             const float* __restrict__ w_out)
{
    int idx = blockIdx.x * 256 + threadIdx.x;
    int which = idx >> 16;
    int n = (idx >> 8) & 255;
    int k = idx & 255;
    float v;
    if (which == 0)      v = w_in[k * 256 + n];
    else if (which == 1) v = (n < NOFF) ? w_off[k * NOFF + n]
                           : (n < NOM) ? w_mask[k * NMSK + (n - NOFF)] : 0.f;
    else                 v = w_out[k * 256 + n];
    split1(v, &g_wth[idx], &g_wtl[idx]);
}

// ---------------------------------------------------------------------------
// x (NCHW) -> g_ah/g_al [m][k] via smem transpose.  grid = 784 (32 m per block)
// ---------------------------------------------------------------------------
__global__ __launch_bounds__(256)
void prep_x(const float* __restrict__ x)
{
    __shared__ float s[32][257];
    const int mb = blockIdx.x * 32;
    const int b = mb / 3136, hw0 = mb % 3136;
    const int lane = threadIdx.x & 31, kw = threadIdx.x >> 5;
#pragma unroll
    for (int p = 0; p < 32; p++) {
        int k = p * 8 + kw;
        s[lane][k] = x[((size_t)(b * 256 + k)) * 3136 + hw0 + lane];
    }
    __syncthreads();
    const int row = threadIdx.x >> 3, seg = threadIdx.x & 7;
    const int m = mb + row, k0 = seg * 32;
    uint32_t hi[16], lo[16];
#pragma unroll
    for (int j = 0; j < 16; j++) {
        float a = s[row][k0 + 2 * j], bv = s[row][k0 + 2 * j + 1];
        hi[j] = hi2(a, bv); lo[j] = lo2(a, bv);
    }
    uint4* dh = (uint4*)(g_ah + (size_t)m * 256 + k0);
    uint4* dl = (uint4*)(g_al + (size_t)m * 256 + k0);
#pragma unroll
    for (int q = 0; q < 4; q++) {
        dh[q] = make_uint4(hi[4*q], hi[4*q+1], hi[4*q+2], hi[4*q+3]);
        dl[q] = make_uint4(lo[4*q], lo[4*q+1], lo[4*q+2], lo[4*q+3]);
    }
}

// ---------------------------------------------------------------------------
// Zero only the padding ring of g_vp (interior fully overwritten by gemm<0>).
// ring cells per image = 58*58 - 56*56 = 228.  228*8 blocks of 256 threads.
// ---------------------------------------------------------------------------
__global__ void zero_border_kernel() {
    int cell = blockIdx.x;            // 0..228*8-1
    int b = cell / 228, r = cell % 228;
    int h, w;
    if (r < 58)        { h = 0;  w = r; }
    else if (r < 116)  { h = 57; w = r - 58; }
    else if (r < 172)  { h = r - 116 + 1; w = 0; }
    else               { h = r - 172 + 1; w = 57; }
    g_vp[((size_t)((b * 58 + h) * 58 + w)) * 256 + threadIdx.x] = 0.f;
}

// ---------------------------------------------------------------------------
// Tensor-core GEMM via mma.sync, bf16 3-term split, fp32 accum.
// cp.async double-buffered K-loop (4 chunks of K=64).
// Block tile 128m x 128n.  W rows = mma A-operand, act rows = B-operand.
// MODE 0: -> g_vp interior (NHWC pad, +b_in)
// MODE 1: -> g_om (216 cols, +b_off/b_mask)
// MODE 2: -> d_out NCHW with folded BN + SiLU
// ---------------------------------------------------------------------------
#define STAGE_BYTES 73728   // 4 tensors * 128 rows * 144 B
#define SMEM_GEMM   (2 * STAGE_BYTES)

template<int MODE>
__global__ __launch_bounds__(256, 1)
void gemm_mma(const float* __restrict__ bias,
              const float* __restrict__ bias2,
              float* __restrict__ Cout,
              const float* __restrict__ bn_g, const float* __restrict__ bn_b,
              const float* __restrict__ bn_mean, const float* __restrict__ bn_var)
{
    extern __shared__ char smem[];
    const uint32_t smem_b = smem_u32(smem);

    const int tid = threadIdx.x, wid = tid >> 5, lane = tid & 31;
    const int g = lane >> 2, tig = lane & 3;
    const int nb0 = blockIdx.x * 128, mb0 = blockIdx.y * 128;
    const int nw4 = wid & 3;    // n-slab (32 rows of W)
    const int mw2 = wid >> 2;   // m-slab (64 act rows)

    const __nv_bfloat16* wth = g_wth + MODE * 65536;
    const __nv_bfloat16* wtl = g_wtl + MODE * 65536;

    // per-thread staging addresses (4 x 16B per tensor per chunk)
    const int r_st  = tid >> 1;             // used via idx decomposition below
    (void)r_st;

    float acc[2][8][4];
#pragma unroll
    for (int a = 0; a < 2; a++)
#pragma unroll
        for (int b = 0; b < 8; b++)
#pragma unroll
            for (int c = 0; c < 4; c++) acc[a][b][c] = 0.f;

    // ---- async stage of one K-chunk into buffer `buf` ----
    auto stage = [&](int buf, int chv) {
        const int k0c = chv * 64;
        const uint32_t base = smem_b + buf * STAGE_BYTES;
#pragma unroll
        for (int i = 0; i < 4; i++) {
            int idx = i * 256 + tid;
            int r = idx >> 3, seg = idx & 7;
            uint32_t so = base + (uint32_t)(r * 144 + seg * 16);
            size_t wof = (size_t)(nb0 + r) * 256 + k0c + seg * 8;
            size_t mof = (size_t)(mb0 + r) * 256 + k0c + seg * 8;
            cpasync16(so,         wth + wof);
            cpasync16(so + 18432, wtl + wof);
            cpasync16(so + 36864, g_ah + mof);
            cpasync16(so + 55296, g_al + mof);
        }
        CP_COMMIT();
    };

    stage(0, 0);

    for (int chv = 0; chv < 4; chv++) {
        if (chv + 1 < 4) stage((chv + 1) & 1, chv + 1);
        if (chv + 1 < 4) { CP_WAIT(1); } else { CP_WAIT(0); }
        __syncthreads();

        char* sbuf = smem + (chv & 1) * STAGE_BYTES;
        char* sWh = sbuf;
        char* sWl = sbuf + 18432;
        char* sMh = sbuf + 36864;
        char* sMl = sbuf + 55296;

#pragma unroll
        for (int ks = 0; ks < 4; ks++) {
            const int kk = ks * 16 + tig * 2;
            uint32_t wh[2][4], wl[2][4], mh[8][2], ml[8][2];
#pragma unroll
            for (int mt = 0; mt < 2; mt++) {
                int r = nw4 * 32 + mt * 16 + g;
                uint32_t o0 = (uint32_t)(r * 144 + kk * 2);
                uint32_t o1 = (uint32_t)((r + 8) * 144 + kk * 2);
                wh[mt][0] = *(uint32_t*)(sWh + o0);
                wh[mt][1] = *(uint32_t*)(sWh + o1);
                wh[mt][2] = *(uint32_t*)(sWh + o0 + 16);
                wh[mt][3] = *(uint32_t*)(sWh + o1 + 16);
                wl[mt][0] = *(uint32_t*)(sWl + o0);
                wl[mt][1] = *(uint32_t*)(sWl + o1);
                wl[mt][2] = *(uint32_t*)(sWl + o0 + 16);
                wl[mt][3] = *(uint32_t*)(sWl + o1 + 16);
            }
#pragma unroll
            for (int nt = 0; nt < 8; nt++) {
                int r = mw2 * 64 + nt * 8 + g;
                uint32_t o = (uint32_t)(r * 144 + kk * 2);
                mh[nt][0] = *(uint32_t*)(sMh + o);
                mh[nt][1] = *(uint32_t*)(sMh + o + 16);
                ml[nt][0] = *(uint32_t*)(sMl + o);
                ml[nt][1] = *(uint32_t*)(sMl + o + 16);
            }
#pragma unroll
            for (int mt = 0; mt < 2; mt++)
#pragma unroll
                for (int nt = 0; nt < 8; nt++)
                    mma16816(acc[mt][nt], wh[mt], mh[nt]);
#pragma unroll
            for (int mt = 0; mt < 2; mt++)
#pragma unroll
                for (int nt = 0; nt < 8; nt++)
                    mma16816(acc[mt][nt], wh[mt], ml[nt]);
#pragma unroll
            for (int mt = 0; mt < 2; mt++)
#pragma unroll
                for (int nt = 0; nt < 8; nt++)
                    mma16816(acc[mt][nt], wl[mt], mh[nt]);
        }
        __syncthreads();
    }

    // ---- stage C tile to smem [m_loc][n_loc], stride 129 (conflict-free cols)
    float* sOut = (float*)smem;
#pragma unroll
    for (int mt = 0; mt < 2; mt++)
#pragma unroll
        for (int nt = 0; nt < 8; nt++) {
            int n_loc = nw4 * 32 + mt * 16 + g;
            int m_loc = mw2 * 64 + nt * 8 + tig * 2;
            sOut[m_loc * 129 + n_loc]            = acc[mt][nt][0];
            sOut[(m_loc + 1) * 129 + n_loc]      = acc[mt][nt][1];
            sOut[m_loc * 129 + n_loc + 8]        = acc[mt][nt][2];
            sOut[(m_loc + 1) * 129 + n_loc + 8]  = acc[mt][nt][3];
        }
    __syncthreads();

    // ---- mode-specific global stores ----
    if (MODE == 0) {
        for (int t = tid; t < 128 * 32; t += 256) {
            int m_loc = t >> 5, c4 = (t & 31) * 4;
            int m = mb0 + m_loc;
            int b = m / 3136, hw = m - b * 3136;
            int h = hw / 56, w = hw - h * 56;
            float4 v;
            v.x = sOut[m_loc * 129 + c4 + 0] + __ldg(&bias[nb0 + c4 + 0]);
            v.y = sOut[m_loc * 129 + c4 + 1] + __ldg(&bias[nb0 + c4 + 1]);
            v.z = sOut[m_loc * 129 + c4 + 2] + __ldg(&bias[nb0 + c4 + 2]);
            v.w = sOut[m_loc * 129 + c4 + 3] + __ldg(&bias[nb0 + c4 + 3]);
            *(float4*)(g_vp + ((size_t)((b * 58 + h + 1) * 58 + (w + 1))) * 256
                       + nb0 + c4) = v;
        }
    } else if (MODE == 1) {
        const int nq = (nb0 == 0) ? 32 : 22;   // float4 cols: 128 or 88 (216-128)
        for (int t = tid; t < 128 * nq; t += 256) {
            int m_loc = t / nq, c4 = (t - m_loc * nq) * 4;
            int n = nb0 + c4;
            float4 v;
            float* sp = &sOut[m_loc * 129 + c4];
            v.x = sp[0] + ((n + 0 < NOFF) ? __ldg(&bias[n + 0]) : __ldg(&bias2[n + 0 - NOFF]));
            v.y = sp[1] + ((n + 1 < NOFF) ? __ldg(&bias[n + 1]) : __ldg(&bias2[n + 1 - NOFF]));
            v.z = sp[2] + ((n + 2 < NOFF) ? __ldg(&bias[n + 2]) : __ldg(&bias2[n + 2 - NOFF]));
            v.w = sp[3] + ((n + 3 < NOFF) ? __ldg(&bias[n + 3]) : __ldg(&bias2[n + 3 - NOFF]));
            *(float4*)(g_om + (size_t)(mb0 + m_loc) * 216 + n) = v;
        }
    } else {
        for (int ni = wid; ni < 128; ni += 8) {
            int n = nb0 + ni;
            float kA = __ldg(&bn_g[n]) * rsqrtf(__ldg(&bn_var[n]) + 1e-5f);
            float kB = (__ldg(&bias[n]) - __ldg(&bn_mean[n])) * kA + __ldg(&bn_b[n]);
#pragma unroll
            for (int mh2 = 0; mh2 < 4; mh2++) {
                int m_loc = mh2 * 32 + lane;
                int m = mb0 + m_loc;
                int b = m / 3136, hw = m - b * 3136;
                float f = sOut[m_loc * 129 + ni] * kA + kB;
                float o = f / (1.f + expf(-f));
                Cout[((size_t)(b * 256 + n)) * 3136 + hw] = o;
            }
        }
    }
}

// ---------------------------------------------------------------------------
// Depthwise 3x3 conv (NCHW in) -> NHWC g_f (pre-LN).
// ---------------------------------------------------------------------------
__global__ __launch_bounds__(256)
void dwconv_kernel(const float* __restrict__ x,
                   const float* __restrict__ dw_w,
                   const float* __restrict__ dw_b)
{
    __shared__ float sx[32 * 177];
    __shared__ float sw_[32 * 9];
    __shared__ float sb_[32];

    const int c0  = blockIdx.x * 32;
    const int h   = blockIdx.y;
    const int b   = blockIdx.z;
    const int tid = threadIdx.x;

    for (int i = tid; i < 288; i += 256) sw_[i] = dw_w[c0 * 9 + i];
    if (tid < 32) sb_[tid] = dw_b[c0 + tid];

    for (int idx = tid; idx < 32 * 3 * 58; idx += 256) {
        int col = idx % 58;
        int r   = (idx / 58) % 3;
        int c   = idx / 174;
        int hh  = h - 1 + r;
        int wwc = col - 1;
        float v = 0.f;
        if (hh >= 0 && hh < 56 && wwc >= 0 && wwc < 56)
            v = x[((size_t)(b * 256 + c0 + c)) * 3136 + hh * 56 + wwc];
        sx[c * 177 + r * 59 + col] = v;
    }
    __syncthreads();

    for (int oi = tid; oi < 32 * 56; oi += 256) {
        int c = oi & 31;
        int w = oi >> 5;
        float accv = sb_[c];
#pragma unroll
        for (int r = 0; r < 3; r++)
#pragma unroll
            for (int j = 0; j < 3; j++)
                accv = fmaf(sx[c * 177 + r * 59 + w + j], sw_[c * 9 + r * 3 + j], accv);
        g_f[((size_t)((b * 56 + h) * 56 + w)) * 256 + c0 + c] = accv;
    }
}

// ---------------------------------------------------------------------------
// LayerNorm (C=256) + exact GELU; warp-per-position, 8 positions per block.
// Writes split bf16 to g_ah/g_al.
// ---------------------------------------------------------------------------
__global__ __launch_bounds__(256)
void ln_gelu_kernel(const float* __restrict__ ln_g,
                    const float* __restrict__ ln_b)
{
    const int warp = threadIdx.x >> 5, lane = threadIdx.x & 31;
    const int m = blockIdx.x * 8 + warp;
    const int k0 = lane * 8;

    const float* src = g_f + (size_t)m * 256 + k0;
    float4 v0 = *(const float4*)src;
    float4 v1 = *(const float4*)(src + 4);
    float e[8] = {v0.x, v0.y, v0.z, v0.w, v1.x, v1.y, v1.z, v1.w};

    float s = 0.f, s2 = 0.f;
#pragma unroll
    for (int j = 0; j < 8; j++) { s += e[j]; s2 += e[j] * e[j]; }
#pragma unroll
    for (int o = 16; o; o >>= 1) {
        s  += __shfl_xor_sync(0xffffffffu, s,  o);
        s2 += __shfl_xor_sync(0xffffffffu, s2, o);
    }
    float mean = s * (1.f / 256.f);
    float var  = s2 * (1.f / 256.f) - mean * mean;
    float rstd = rsqrtf(var + 1e-5f);

    uint32_t hi[4], lo[4];
#pragma unroll
    for (int j = 0; j < 4; j++) {
        float a = (e[2*j]   - mean) * rstd * __ldg(&ln_g[k0 + 2*j])   + __ldg(&ln_b[k0 + 2*j]);
        float b = (e[2*j+1] - mean) * rstd * __ldg(&ln_g[k0 + 2*j+1]) + __ldg(&ln_b[k0 + 2*j+1]);
        a = 0.5f * a * (1.f + erff(a * 0.70710678118654752f));
        b = 0.5f * b * (1.f + erff(b * 0.70710678118654752f));
        hi[j] = hi2(a, b); lo[j] = lo2(a, b);
    }
    *(uint4*)(g_ah + (size_t)m * 256 + k0) = make_uint4(hi[0], hi[1], hi[2], hi[3]);
    *(uint4*)(g_al + (size_t)m * 256 + k0) = make_uint4(lo[0], lo[1], lo[2], lo[3]);
}

// ---------------------------------------------------------------------------
// Deformable sampling; writes split bf16 to g_ah/g_al for the final GEMM.
// ---------------------------------------------------------------------------
__global__ __launch_bounds__(256)
void sample_kernel()
{
    const int m    = blockIdx.x;
    const int b    = m / 3136;
    const int hw   = m - b * 3136;
    const int h    = hw / 56;
    const int w    = hw - h * 56;
    const int g    = threadIdx.x >> 5;
    const int lane = threadIdx.x & 31;

    const float* row = g_om + (size_t)m * 216;

    float offx[9], offy[9], mk[9];
    float mx = -3.0e38f;
#pragma unroll
    for (int p = 0; p < 9; p++) {
        offx[p] = row[g * 18 + 2 * p];
        offy[p] = row[g * 18 + 2 * p + 1];
        mk[p]   = row[144 + g * 9 + p];
        mx = fmaxf(mx, mk[p]);
    }
    float sum = 0.f;
#pragma unroll
    for (int p = 0; p < 9; p++) { mk[p] = expf(mk[p] - mx); sum += mk[p]; }
    const float inv = 1.f / sum;

    float acc = 0.f;
    const float* vpg = g_vp + (size_t)b * 58 * 58 * 256 + g * 32 + lane;

#pragma unroll
    for (int p = 0; p < 9; p++) {
        float px = (float)(w + (p / 3)) + offx[p];
        float py = (float)(h + (p % 3)) + offy[p];
        float x0f = floorf(px), y0f = floorf(py);
        float wx = px - x0f, wy = py - y0f;
        int x0 = (int)x0f, y0 = (int)y0f;
        int x1 = x0 + 1,   y1 = y0 + 1;
        float vx0 = (x0 >= 0 && x0 < 58) ? 1.f : 0.f;
        float vx1 = (x1 >= 0 && x1 < 58) ? 1.f : 0.f;
        float vy0 = (y0 >= 0 && y0 < 58) ? 1.f : 0.f;
        float vy1 = (y1 >= 0 && y1 < 58) ? 1.f : 0.f;
        int x0c = min(max(x0, 0), 57), x1c = min(max(x1, 0), 57);
        int y0c = min(max(y0, 0), 57), y1c = min(max(y1, 0), 57);

        float mp  = mk[p] * inv;
        float w00 = (1.f - wx) * (1.f - wy) * vx0 * vy0 * mp;
        float w01 = wx * (1.f - wy) * vx1 * vy0 * mp;
        float w10 = (1.f - wx) * wy * vx0 * vy1 * mp;
        float w11 = wx * wy * vx1 * vy1 * mp;

        acc += w00 * vpg[(y0c * 58 + x0c) * 256]
             + w01 * vpg[(y0c * 58 + x1c) * 256]
             + w10 * vpg[(y1c * 58 + x0c) * 256]
             + w11 * vpg[(y1c * 58 + x1c) * 256];
    }
    int c = g * 32 + lane;
    split1(acc, &g_ah[(size_t)m * 256 + c], &g_al[(size_t)m * 256 + c]);
}

// ---------------------------------------------------------------------------
extern "C" void kernel_launch(void* const* d_in, const int* in_sizes, int n_in,
                              void* d_out, int out_size)
{
    const float* x      = (const float*)d_in[0];
    const float* b_in   = (const float*)d_in[2];
    const float* dw_w   = (const float*)d_in[3];
    const float* dw_b   = (const float*)d_in[4];
    const float* ln_g   = (const float*)d_in[5];
    const float* ln_b   = (const float*)d_in[6];
    const float* b_off  = (const float*)d_in[8];
    const float* b_mask = (const float*)d_in[10];
    const float* b_out  = (const float*)d_in[12];
    const float* bn_g   = (const float*)d_in[13];
    const float* bn_b   = (const float*)d_in[14];
    const float* bn_mean= (const float*)d_in[15];
    const float* bn_var = (const float*)d_in[16];
    float* out = (float*)d_out;

    cudaFuncSetAttribute(gemm_mma<0>, cudaFuncAttributeMaxDynamicSharedMemorySize, SMEM_GEMM);
    cudaFuncSetAttribute(gemm_mma<1>, cudaFuncAttributeMaxDynamicSharedMemorySize, SMEM_GEMM);
    cudaFuncSetAttribute(gemm_mma<2>, cudaFuncAttributeMaxDynamicSharedMemorySize, SMEM_GEMM);

    dim3 ggrid(2, 196);

    prep_weights<<<768, 256>>>((const float*)d_in[1], (const float*)d_in[7],
                               (const float*)d_in[9], (const float*)d_in[11]);
    prep_x<<<784, 256>>>(x);
    zero_border_kernel<<<228 * 8, 256>>>();
    // input projection -> padded vp (NHWC)
    gemm_mma<0><<<ggrid, 256, SMEM_GEMM>>>(b_in, nullptr, nullptr,
                                           nullptr, nullptr, nullptr, nullptr);
    // offset/mask branch
    dwconv_kernel<<<dim3(8, 56, 8), 256>>>(x, dw_w, dw_b);
    ln_gelu_kernel<<<3136, 256>>>(ln_g, ln_b);
    gemm_mma<1><<<ggrid, 256, SMEM_GEMM>>>(b_off, b_mask, nullptr,
                                           nullptr, nullptr, nullptr, nullptr);
    // deformable bilinear sampling + mask aggregation
    sample_kernel<<<25088, 256>>>();
    // output projection + BN + SiLU -> NCHW
    gemm_mma<2><<<ggrid, 256, SMEM_GEMM>>>(b_out, nullptr, out,
                                           bn_g, bn_b, bn_mean, bn_var);
}

// round 6
// speedup vs baseline: 1.4710x; 1.0643x over previous
#include <cuda_runtime.h>
#include <cuda_bf16.h>
#include <math.h>
#include <stdint.h>

// Problem constants
#define BB    8
#define CC    256
#define HH    56
#define WW    56
#define HIN   58
#define WIN   58
#define MTOT  25088      // B*H*W
#define NOFF  144
#define NMSK  72
#define NOM   216

// Scratch (device globals; no runtime allocation allowed)
__device__ float g_vp[BB*HIN*WIN*CC];        // padded projected features, NHWC fp32
__device__ float g_f [MTOT*CC];              // dwconv output (pre-LN), NHWC fp32
__device__ float g_om[MTOT*NOM];             // [offset(144) | mask(72)] logits
__device__ __nv_bfloat16 g_ah[MTOT*CC];      // activation bf16 hi   [m][k]
__device__ __nv_bfloat16 g_al[MTOT*CC];      // activation bf16 lo   [m][k]
__device__ __nv_bfloat16 g_wth[3*65536];     // weights^T [which][n][k], hi
__device__ __nv_bfloat16 g_wtl[3*65536];     // weights^T lo

// ---------------------------------------------------------------------------
// fp32 -> bf16 hi/lo split helpers
// ---------------------------------------------------------------------------
__device__ __forceinline__ uint32_t hibits(float v) {
    uint32_t u = __float_as_uint(v);
    return (u + 0x7FFFu + ((u >> 16) & 1u)) & 0xFFFF0000u;
}
__device__ __forceinline__ uint32_t hi2(float a, float b) {
    return (hibits(a) >> 16) | (hibits(b) & 0xFFFF0000u);
}
__device__ __forceinline__ uint32_t lo2(float a, float b) {
    float la = a - __uint_as_float(hibits(a));
    float lb = b - __uint_as_float(hibits(b));
    uint32_t r;
    asm("cvt.rn.satfinite.bf16x2.f32 %0, %1, %2;" : "=r"(r) : "f"(lb), "f"(la));
    return r;
}
__device__ __forceinline__ void split1(float v, __nv_bfloat16* ph, __nv_bfloat16* pl) {
    uint32_t hb = hibits(v);
    __nv_bfloat16_raw hr; hr.x = (unsigned short)(hb >> 16);
    *ph = __nv_bfloat16(hr);
    *pl = __float2bfloat16(v - __uint_as_float(hb));
}

// mma.sync m16n8k16 bf16 -> f32 (portable tensor-core path)
__device__ __forceinline__ void mma16816(float* c, const uint32_t* a, const uint32_t* b) {
    asm volatile(
        "mma.sync.aligned.m16n8k16.row.col.f32.bf16.bf16.f32 "
        "{%0,%1,%2,%3}, {%4,%5,%6,%7}, {%8,%9}, {%0,%1,%2,%3};"
        : "+f"(c[0]), "+f"(c[1]), "+f"(c[2]), "+f"(c[3])
        : "r"(a[0]), "r"(a[1]), "r"(a[2]), "r"(a[3]), "r"(b[0]), "r"(b[1]));
}

__device__ __forceinline__ uint32_t smem_u32(const void* p) {
    uint32_t a;
    asm("{ .reg .u64 t; cvta.to.shared.u64 t, %1; cvt.u32.u64 %0, t; }"
        : "=r"(a) : "l"(p));
    return a;
}
__device__ __forceinline__ void cpasync16(uint32_t dst, const void* src) {
    asm volatile("cp.async.cg.shared.global [%0], [%1], 16;" :: "r"(dst), "l"(src));
}
#define CP_COMMIT()  asm volatile("cp.async.commit_group;" ::: "memory")
#define CP_WAIT(n)   asm volatile("cp.async.wait_group %0;" :: "n"(n) : "memory")

// ---------------------------------------------------------------------------
// Weight prep: transpose + bf16 hi/lo split.  idx = which*65536 + n*256 + k
// ---------------------------------------------------------------------------
__global__ void prep_weights(const float* __restrict__ w_in,
                             const float* __restrict__ w_off,
                             const float* __restrict__ w_mask,
                             const float* __restrict__ w_out)
{
    int idx = blockIdx.x * 256 + threadIdx.x;
    int which = idx >> 16;
    int n = (idx >> 8) & 255;
    int k = idx & 255;
    float v;
    if (which == 0)      v = w_in[k * 256 + n];
    else if (which == 1) v = (n < NOFF) ? w_off[k * NOFF + n]
                           : (n < NOM) ? w_mask[k * NMSK + (n - NOFF)] : 0.f;
    else                 v = w_out[k * 256 + n];
    split1(v, &g_wth[idx], &g_wtl[idx]);
}

// ---------------------------------------------------------------------------
// x (NCHW) -> g_ah/g_al [m][k] via smem transpose.  grid = 784 (32 m per block)
// ---------------------------------------------------------------------------
__global__ __launch_bounds__(256)
void prep_x(const float* __restrict__ x)
{
    __shared__ float s[32][257];
    const int mb = blockIdx.x * 32;
    const int b = mb / 3136, hw0 = mb % 3136;
    const int lane = threadIdx.x & 31, kw = threadIdx.x >> 5;
#pragma unroll
    for (int p = 0; p < 32; p++) {
        int k = p * 8 + kw;
        s[lane][k] = x[((size_t)(b * 256 + k)) * 3136 + hw0 + lane];
    }
    __syncthreads();
    const int row = threadIdx.x >> 3, seg = threadIdx.x & 7;
    const int m = mb + row, k0 = seg * 32;
    uint32_t hi[16], lo[16];
#pragma unroll
    for (int j = 0; j < 16; j++) {
        float a = s[row][k0 + 2 * j], bv = s[row][k0 + 2 * j + 1];
        hi[j] = hi2(a, bv); lo[j] = lo2(a, bv);
    }
    uint4* dh = (uint4*)(g_ah + (size_t)m * 256 + k0);
    uint4* dl = (uint4*)(g_al + (size_t)m * 256 + k0);
#pragma unroll
    for (int q = 0; q < 4; q++) {
        dh[q] = make_uint4(hi[4*q], hi[4*q+1], hi[4*q+2], hi[4*q+3]);
        dl[q] = make_uint4(lo[4*q], lo[4*q+1], lo[4*q+2], lo[4*q+3]);
    }
}

// ---------------------------------------------------------------------------
// Zero only the padding ring of g_vp (interior fully overwritten by gemm<0>).
// ---------------------------------------------------------------------------
__global__ void zero_border_kernel() {
    int cell = blockIdx.x;            // 0..228*8-1
    int b = cell / 228, r = cell % 228;
    int h, w;
    if (r < 58)        { h = 0;  w = r; }
    else if (r < 116)  { h = 57; w = r - 58; }
    else if (r < 172)  { h = r - 116 + 1; w = 0; }
    else               { h = r - 172 + 1; w = 57; }
    g_vp[((size_t)((b * 58 + h) * 58 + w)) * 256 + threadIdx.x] = 0.f;
}

// ---------------------------------------------------------------------------
// Tensor-core GEMM: bf16 3-term split, fp32 accum, cp.async double buffer.
// Block tile 128m x 64n (2 CTAs/SM).  8 warps = 2 n-slabs x 4 m-slabs.
// MODE 0: -> g_vp interior (+b_in) | MODE 1: -> g_om | MODE 2: -> out BN+SiLU
// ---------------------------------------------------------------------------
#define SW_BYTES   9216    // 64 rows * 144 B
#define SM_BYTES   18432   // 128 rows * 144 B
#define STG_BYTES  55296   // 2*(SW+SM)
#define SMEM_GEMM  (2 * STG_BYTES)

template<int MODE>
__global__ __launch_bounds__(256, 2)
void gemm_mma(const float* __restrict__ bias,
              const float* __restrict__ bias2,
              float* __restrict__ Cout,
              const float* __restrict__ bn_g, const float* __restrict__ bn_b,
              const float* __restrict__ bn_mean, const float* __restrict__ bn_var)
{
    extern __shared__ char smem[];
    const uint32_t smem_b = smem_u32(smem);

    const int tid = threadIdx.x, wid = tid >> 5, lane = tid & 31;
    const int g = lane >> 2, tig = lane & 3;
    const int nb0 = blockIdx.x * 64, mb0 = blockIdx.y * 128;
    const int nw = wid & 1;     // n-slab (32 W rows)
    const int mw = wid >> 1;    // m-slab (32 act rows)

    const __nv_bfloat16* wth = g_wth + MODE * 65536;
    const __nv_bfloat16* wtl = g_wtl + MODE * 65536;

    float acc[2][4][4];
#pragma unroll
    for (int a = 0; a < 2; a++)
#pragma unroll
        for (int b = 0; b < 4; b++)
#pragma unroll
            for (int c = 0; c < 4; c++) acc[a][b][c] = 0.f;

    auto stage = [&](int buf, int chv) {
        const int k0c = chv * 64;
        const uint32_t base = smem_b + buf * STG_BYTES;
#pragma unroll
        for (int i = 0; i < 2; i++) {              // W: 64 rows, hi+lo
            int idx = i * 256 + tid;
            int r = idx >> 3, seg = idx & 7;
            uint32_t so = base + (uint32_t)(r * 144 + seg * 16);
            size_t wof = (size_t)(nb0 + r) * 256 + k0c + seg * 8;
            cpasync16(so,            wth + wof);
            cpasync16(so + SW_BYTES, wtl + wof);
        }
#pragma unroll
        for (int i = 0; i < 4; i++) {              // M: 128 rows, hi+lo
            int idx = i * 256 + tid;
            int r = idx >> 3, seg = idx & 7;
            uint32_t so = base + 2 * SW_BYTES + (uint32_t)(r * 144 + seg * 16);
            size_t mof = (size_t)(mb0 + r) * 256 + k0c + seg * 8;
            cpasync16(so,            g_ah + mof);
            cpasync16(so + SM_BYTES, g_al + mof);
        }
        CP_COMMIT();
    };

    stage(0, 0);

    for (int chv = 0; chv < 4; chv++) {
        if (chv + 1 < 4) { stage((chv + 1) & 1, chv + 1); CP_WAIT(1); }
        else             { CP_WAIT(0); }
        __syncthreads();

        char* sbuf = smem + (chv & 1) * STG_BYTES;
        char* sWh = sbuf;
        char* sWl = sbuf + SW_BYTES;
        char* sMh = sbuf + 2 * SW_BYTES;
        char* sMl = sbuf + 2 * SW_BYTES + SM_BYTES;

#pragma unroll
        for (int ks = 0; ks < 4; ks++) {
            const int kk = ks * 16 + tig * 2;
            uint32_t wh[2][4], wl[2][4], mh[4][2], ml[4][2];
#pragma unroll
            for (int mt = 0; mt < 2; mt++) {
                int r = nw * 32 + mt * 16 + g;
                uint32_t o0 = (uint32_t)(r * 144 + kk * 2);
                uint32_t o1 = (uint32_t)((r + 8) * 144 + kk * 2);
                wh[mt][0] = *(uint32_t*)(sWh + o0);
                wh[mt][1] = *(uint32_t*)(sWh + o1);
                wh[mt][2] = *(uint32_t*)(sWh + o0 + 16);
                wh[mt][3] = *(uint32_t*)(sWh + o1 + 16);
                wl[mt][0] = *(uint32_t*)(sWl + o0);
                wl[mt][1] = *(uint32_t*)(sWl + o1);
                wl[mt][2] = *(uint32_t*)(sWl + o0 + 16);
                wl[mt][3] = *(uint32_t*)(sWl + o1 + 16);
            }
#pragma unroll
            for (int nt = 0; nt < 4; nt++) {
                int r = mw * 32 + nt * 8 + g;
                uint32_t o = (uint32_t)(r * 144 + kk * 2);
                mh[nt][0] = *(uint32_t*)(sMh + o);
                mh[nt][1] = *(uint32_t*)(sMh + o + 16);
                ml[nt][0] = *(uint32_t*)(sMl + o);
                ml[nt][1] = *(uint32_t*)(sMl + o + 16);
            }
#pragma unroll
            for (int mt = 0; mt < 2; mt++)
#pragma unroll
                for (int nt = 0; nt < 4; nt++)
                    mma16816(acc[mt][nt], wh[mt], mh[nt]);
#pragma unroll
            for (int mt = 0; mt < 2; mt++)
#pragma unroll
                for (int nt = 0; nt < 4; nt++)
                    mma16816(acc[mt][nt], wh[mt], ml[nt]);
#pragma unroll
            for (int mt = 0; mt < 2; mt++)
#pragma unroll
                for (int nt = 0; nt < 4; nt++)
                    mma16816(acc[mt][nt], wl[mt], mh[nt]);
        }
        __syncthreads();
    }

    // ---- stage C tile [m_loc][n_loc], stride 65 ----
    float* sOut = (float*)smem;
#pragma unroll
    for (int mt = 0; mt < 2; mt++)
#pragma unroll
        for (int nt = 0; nt < 4; nt++) {
            int n_loc = nw * 32 + mt * 16 + g;
            int m_loc = mw * 32 + nt * 8 + tig * 2;
            sOut[m_loc * 65 + n_loc]           = acc[mt][nt][0];
            sOut[(m_loc + 1) * 65 + n_loc]     = acc[mt][nt][1];
            sOut[m_loc * 65 + n_loc + 8]       = acc[mt][nt][2];
            sOut[(m_loc + 1) * 65 + n_loc + 8] = acc[mt][nt][3];
        }
    __syncthreads();

    // ---- mode-specific global stores ----
    if (MODE == 0) {
        for (int t = tid; t < 128 * 16; t += 256) {
            int m_loc = t >> 4, c4 = (t & 15) * 4;
            int m = mb0 + m_loc;
            int b = m / 3136, hw = m - b * 3136;
            int h = hw / 56, w = hw - h * 56;
            float4 v;
            v.x = sOut[m_loc * 65 + c4 + 0] + __ldg(&bias[nb0 + c4 + 0]);
            v.y = sOut[m_loc * 65 + c4 + 1] + __ldg(&bias[nb0 + c4 + 1]);
            v.z = sOut[m_loc * 65 + c4 + 2] + __ldg(&bias[nb0 + c4 + 2]);
            v.w = sOut[m_loc * 65 + c4 + 3] + __ldg(&bias[nb0 + c4 + 3]);
            *(float4*)(g_vp + ((size_t)((b * 58 + h + 1) * 58 + (w + 1))) * 256
                       + nb0 + c4) = v;
        }
    } else if (MODE == 1) {
        int navail = NOM - nb0; if (navail > 64) navail = 64;
        if (navail > 0) {
            const int nq = navail >> 2;
            for (int t = tid; t < 128 * nq; t += 256) {
                int m_loc = t / nq, c4 = (t - m_loc * nq) * 4;
                int n = nb0 + c4;
                float4 v;
                float* sp = &sOut[m_loc * 65 + c4];
                v.x = sp[0] + ((n + 0 < NOFF) ? __ldg(&bias[n + 0]) : __ldg(&bias2[n + 0 - NOFF]));
                v.y = sp[1] + ((n + 1 < NOFF) ? __ldg(&bias[n + 1]) : __ldg(&bias2[n + 1 - NOFF]));
                v.z = sp[2] + ((n + 2 < NOFF) ? __ldg(&bias[n + 2]) : __ldg(&bias2[n + 2 - NOFF]));
                v.w = sp[3] + ((n + 3 < NOFF) ? __ldg(&bias[n + 3]) : __ldg(&bias2[n + 3 - NOFF]));
                *(float4*)(g_om + (size_t)(mb0 + m_loc) * 216 + n) = v;
            }
        }
    } else {
        for (int ni = wid; ni < 64; ni += 8) {
            int n = nb0 + ni;
            float kA = __ldg(&bn_g[n]) * rsqrtf(__ldg(&bn_var[n]) + 1e-5f);
            float kB = (__ldg(&bias[n]) - __ldg(&bn_mean[n])) * kA + __ldg(&bn_b[n]);
#pragma unroll
            for (int mh2 = 0; mh2 < 4; mh2++) {
                int m_loc = mh2 * 32 + lane;
                int m = mb0 + m_loc;
                int b = m / 3136, hw = m - b * 3136;
                float f = sOut[m_loc * 65 + ni] * kA + kB;
                float o = f / (1.f + expf(-f));
                Cout[((size_t)(b * 256 + n)) * 3136 + hw] = o;
            }
        }
    }
}

// ---------------------------------------------------------------------------
// Depthwise 3x3 conv (NCHW in) -> NHWC g_f (pre-LN).
// ---------------------------------------------------------------------------
__global__ __launch_bounds__(256)
void dwconv_kernel(const float* __restrict__ x,
                   const float* __restrict__ dw_w,
                   const float* __restrict__ dw_b)
{
    __shared__ float sx[32 * 177];
    __shared__ float sw_[32 * 9];
    __shared__ float sb_[32];

    const int c0  = blockIdx.x * 32;
    const int h   = blockIdx.y;
    const int b   = blockIdx.z;
    const int tid = threadIdx.x;

    for (int i = tid; i < 288; i += 256) sw_[i] = dw_w[c0 * 9 + i];
    if (tid < 32) sb_[tid] = dw_b[c0 + tid];

    for (int idx = tid; idx < 32 * 3 * 58; idx += 256) {
        int col = idx % 58;
        int r   = (idx / 58) % 3;
        int c   = idx / 174;
        int hh  = h - 1 + r;
        int wwc = col - 1;
        float v = 0.f;
        if (hh >= 0 && hh < 56 && wwc >= 0 && wwc < 56)
            v = x[((size_t)(b * 256 + c0 + c)) * 3136 + hh * 56 + wwc];
        sx[c * 177 + r * 59 + col] = v;
    }
    __syncthreads();

    for (int oi = tid; oi < 32 * 56; oi += 256) {
        int c = oi & 31;
        int w = oi >> 5;
        float accv = sb_[c];
#pragma unroll
        for (int r = 0; r < 3; r++)
#pragma unroll
            for (int j = 0; j < 3; j++)
                accv = fmaf(sx[c * 177 + r * 59 + w + j], sw_[c * 9 + r * 3 + j], accv);
        g_f[((size_t)((b * 56 + h) * 56 + w)) * 256 + c0 + c] = accv;
    }
}

// ---------------------------------------------------------------------------
// LayerNorm (C=256) + exact GELU; warp-per-position; writes split bf16.
// ---------------------------------------------------------------------------
__global__ __launch_bounds__(256)
void ln_gelu_kernel(const float* __restrict__ ln_g,
                    const float* __restrict__ ln_b)
{
    const int warp = threadIdx.x >> 5, lane = threadIdx.x & 31;
    const int m = blockIdx.x * 8 + warp;
    const int k0 = lane * 8;

    const float* src = g_f + (size_t)m * 256 + k0;
    float4 v0 = *(const float4*)src;
    float4 v1 = *(const float4*)(src + 4);
    float e[8] = {v0.x, v0.y, v0.z, v0.w, v1.x, v1.y, v1.z, v1.w};

    float s = 0.f, s2 = 0.f;
#pragma unroll
    for (int j = 0; j < 8; j++) { s += e[j]; s2 += e[j] * e[j]; }
#pragma unroll
    for (int o = 16; o; o >>= 1) {
        s  += __shfl_xor_sync(0xffffffffu, s,  o);
        s2 += __shfl_xor_sync(0xffffffffu, s2, o);
    }
    float mean = s * (1.f / 256.f);
    float var  = s2 * (1.f / 256.f) - mean * mean;
    float rstd = rsqrtf(var + 1e-5f);

    uint32_t hi[4], lo[4];
#pragma unroll
    for (int j = 0; j < 4; j++) {
        float a = (e[2*j]   - mean) * rstd * __ldg(&ln_g[k0 + 2*j])   + __ldg(&ln_b[k0 + 2*j]);
        float b = (e[2*j+1] - mean) * rstd * __ldg(&ln_g[k0 + 2*j+1]) + __ldg(&ln_b[k0 + 2*j+1]);
        a = 0.5f * a * (1.f + erff(a * 0.70710678118654752f));
        b = 0.5f * b * (1.f + erff(b * 0.70710678118654752f));
        hi[j] = hi2(a, b); lo[j] = lo2(a, b);
    }
    *(uint4*)(g_ah + (size_t)m * 256 + k0) = make_uint4(hi[0], hi[1], hi[2], hi[3]);
    *(uint4*)(g_al + (size_t)m * 256 + k0) = make_uint4(lo[0], lo[1], lo[2], lo[3]);
}

// ---------------------------------------------------------------------------
// Deformable sampling. grid (3136, 8): block = 8 consecutive positions x one
// group -> overlapping bilinear footprints hit in L1. Warp w: m = m0*8+w.
// ---------------------------------------------------------------------------
__global__ __launch_bounds__(256)
void sample_kernel()
{
    const int wi   = threadIdx.x >> 5;
    const int lane = threadIdx.x & 31;
    const int m    = blockIdx.x * 8 + wi;
    const int g    = blockIdx.y;

    const int b    = m / 3136;
    const int hw   = m - b * 3136;
    const int h    = hw / 56;
    const int w    = hw - h * 56;

    const float* row = g_om + (size_t)m * 216;

    float offx[9], offy[9], mk[9];
    float mx = -3.0e38f;
#pragma unroll
    for (int p = 0; p < 9; p++) {
        offx[p] = row[g * 18 + 2 * p];
        offy[p] = row[g * 18 + 2 * p + 1];
        mk[p]   = row[144 + g * 9 + p];
        mx = fmaxf(mx, mk[p]);
    }
    float sum = 0.f;
#pragma unroll
    for (int p = 0; p < 9; p++) { mk[p] = expf(mk[p] - mx); sum += mk[p]; }
    const float inv = 1.f / sum;

    float acc = 0.f;
    const float* vpg = g_vp + (size_t)b * 58 * 58 * 256 + g * 32 + lane;

#pragma unroll
    for (int p = 0; p < 9; p++) {
        float px = (float)(w + (p / 3)) + offx[p];
        float py = (float)(h + (p % 3)) + offy[p];
        float x0f = floorf(px), y0f = floorf(py);
        float wx = px - x0f, wy = py - y0f;
        int x0 = (int)x0f, y0 = (int)y0f;
        int x1 = x0 + 1,   y1 = y0 + 1;
        float vx0 = (x0 >= 0 && x0 < 58) ? 1.f : 0.f;
        float vx1 = (x1 >= 0 && x1 < 58) ? 1.f : 0.f;
        float vy0 = (y0 >= 0 && y0 < 58) ? 1.f : 0.f;
        float vy1 = (y1 >= 0 && y1 < 58) ? 1.f : 0.f;
        int x0c = min(max(x0, 0), 57), x1c = min(max(x1, 0), 57);
        int y0c = min(max(y0, 0), 57), y1c = min(max(y1, 0), 57);

        float mp  = mk[p] * inv;
        float w00 = (1.f - wx) * (1.f - wy) * vx0 * vy0 * mp;
        float w01 = wx * (1.f - wy) * vx1 * vy0 * mp;
        float w10 = (1.f - wx) * wy * vx0 * vy1 * mp;
        float w11 = wx * wy * vx1 * vy1 * mp;

        acc += w00 * vpg[(y0c * 58 + x0c) * 256]
             + w01 * vpg[(y0c * 58 + x1c) * 256]
             + w10 * vpg[(y1c * 58 + x0c) * 256]
             + w11 * vpg[(y1c * 58 + x1c) * 256];
    }
    int c = g * 32 + lane;
    split1(acc, &g_ah[(size_t)m * 256 + c], &g_al[(size_t)m * 256 + c]);
}

// ---------------------------------------------------------------------------
extern "C" void kernel_launch(void* const* d_in, const int* in_sizes, int n_in,
                              void* d_out, int out_size)
{
    const float* x      = (const float*)d_in[0];
    const float* b_in   = (const float*)d_in[2];
    const float* dw_w   = (const float*)d_in[3];
    const float* dw_b   = (const float*)d_in[4];
    const float* ln_g   = (const float*)d_in[5];
    const float* ln_b   = (const float*)d_in[6];
    const float* b_off  = (const float*)d_in[8];
    const float* b_mask = (const float*)d_in[10];
    const float* b_out  = (const float*)d_in[12];
    const float* bn_g   = (const float*)d_in[13];
    const float* bn_b   = (const float*)d_in[14];
    const float* bn_mean= (const float*)d_in[15];
    const float* bn_var = (const float*)d_in[16];
    float* out = (float*)d_out;

    cudaFuncSetAttribute(gemm_mma<0>, cudaFuncAttributeMaxDynamicSharedMemorySize, SMEM_GEMM);
    cudaFuncSetAttribute(gemm_mma<1>, cudaFuncAttributeMaxDynamicSharedMemorySize, SMEM_GEMM);
    cudaFuncSetAttribute(gemm_mma<2>, cudaFuncAttributeMaxDynamicSharedMemorySize, SMEM_GEMM);

    dim3 ggrid(4, 196);

    prep_weights<<<768, 256>>>((const float*)d_in[1], (const float*)d_in[7],
                               (const float*)d_in[9], (const float*)d_in[11]);
    prep_x<<<784, 256>>>(x);
    zero_border_kernel<<<228 * 8, 256>>>();
    // input projection -> padded vp (NHWC)
    gemm_mma<0><<<ggrid, 256, SMEM_GEMM>>>(b_in, nullptr, nullptr,
                                           nullptr, nullptr, nullptr, nullptr);
    // offset/mask branch
    dwconv_kernel<<<dim3(8, 56, 8), 256>>>(x, dw_w, dw_b);
    ln_gelu_kernel<<<3136, 256>>>(ln_g, ln_b);
    gemm_mma<1><<<ggrid, 256, SMEM_GEMM>>>(b_off, b_mask, nullptr,
                                           nullptr, nullptr, nullptr, nullptr);
    // deformable bilinear sampling + mask aggregation
    sample_kernel<<<dim3(3136, 8), 256>>>();
    // output projection + BN + SiLU -> NCHW
    gemm_mma<2><<<ggrid, 256, SMEM_GEMM>>>(b_out, nullptr, out,
                                           bn_g, bn_b, bn_mean, bn_var);
}

// round 7
// speedup vs baseline: 1.4730x; 1.0014x over previous
#include <cuda_runtime.h>
#include <cuda_bf16.h>
#include <math.h>
#include <stdint.h>

// Problem constants
#define BB    8
#define CC    256
#define HH    56
#define WW    56
#define HIN   58
#define WIN   58
#define MTOT  25088      // B*H*W
#define NOFF  144
#define NMSK  72
#define NOM   216

// Scratch (device globals; no runtime allocation allowed)
__device__ float g_vp[BB*HIN*WIN*CC];        // padded projected features, NHWC fp32
__device__ float g_f [MTOT*CC];              // dwconv output (pre-LN), NHWC fp32
__device__ float g_om[MTOT*NOM];             // [offset(144) | mask(72)] logits
__device__ __nv_bfloat16 g_ah[MTOT*CC];      // activation bf16 hi   [m][k]
__device__ __nv_bfloat16 g_al[MTOT*CC];      // activation bf16 lo   [m][k]
__device__ __nv_bfloat16 g_wth[3*65536];     // weights^T [which][n][k], hi
__device__ __nv_bfloat16 g_wtl[3*65536];     // weights^T lo

// ---------------------------------------------------------------------------
// fp32 -> bf16 hi/lo split helpers
// ---------------------------------------------------------------------------
__device__ __forceinline__ uint32_t hibits(float v) {
    uint32_t u = __float_as_uint(v);
    return (u + 0x7FFFu + ((u >> 16) & 1u)) & 0xFFFF0000u;
}
__device__ __forceinline__ uint32_t hi2(float a, float b) {
    return (hibits(a) >> 16) | (hibits(b) & 0xFFFF0000u);
}
__device__ __forceinline__ uint32_t lo2(float a, float b) {
    float la = a - __uint_as_float(hibits(a));
    float lb = b - __uint_as_float(hibits(b));
    uint32_t r;
    asm("cvt.rn.satfinite.bf16x2.f32 %0, %1, %2;" : "=r"(r) : "f"(lb), "f"(la));
    return r;
}
__device__ __forceinline__ void split1(float v, __nv_bfloat16* ph, __nv_bfloat16* pl) {
    uint32_t hb = hibits(v);
    __nv_bfloat16_raw hr; hr.x = (unsigned short)(hb >> 16);
    *ph = __nv_bfloat16(hr);
    *pl = __float2bfloat16(v - __uint_as_float(hb));
}

// mma.sync m16n8k16 bf16 -> f32 (portable tensor-core path)
__device__ __forceinline__ void mma16816(float* c, const uint32_t* a, const uint32_t* b) {
    asm volatile(
        "mma.sync.aligned.m16n8k16.row.col.f32.bf16.bf16.f32 "
        "{%0,%1,%2,%3}, {%4,%5,%6,%7}, {%8,%9}, {%0,%1,%2,%3};"
        : "+f"(c[0]), "+f"(c[1]), "+f"(c[2]), "+f"(c[3])
        : "r"(a[0]), "r"(a[1]), "r"(a[2]), "r"(a[3]), "r"(b[0]), "r"(b[1]));
}

// ldmatrix x4: fills 4 fragment registers from 4 8x8 b16 tiles in one op
__device__ __forceinline__ void ldsm4(uint32_t* r, uint32_t a) {
    asm volatile("ldmatrix.sync.aligned.m8n8.x4.shared.b16 {%0,%1,%2,%3}, [%4];"
        : "=r"(r[0]), "=r"(r[1]), "=r"(r[2]), "=r"(r[3]) : "r"(a));
}

__device__ __forceinline__ uint32_t smem_u32(const void* p) {
    uint32_t a;
    asm("{ .reg .u64 t; cvta.to.shared.u64 t, %1; cvt.u32.u64 %0, t; }"
        : "=r"(a) : "l"(p));
    return a;
}
__device__ __forceinline__ void cpasync16(uint32_t dst, const void* src) {
    asm volatile("cp.async.cg.shared.global [%0], [%1], 16;" :: "r"(dst), "l"(src));
}
#define CP_COMMIT()  asm volatile("cp.async.commit_group;" ::: "memory")
#define CP_WAIT(n)   asm volatile("cp.async.wait_group %0;" :: "n"(n) : "memory")

// ---------------------------------------------------------------------------
// Weight prep: transpose + bf16 hi/lo split.  idx = which*65536 + n*256 + k
// ---------------------------------------------------------------------------
__global__ void prep_weights(const float* __restrict__ w_in,
                             const float* __restrict__ w_off,
                             const float* __restrict__ w_mask,
                             const float* __restrict__ w_out)
{
    int idx = blockIdx.x * 256 + threadIdx.x;
    int which = idx >> 16;
    int n = (idx >> 8) & 255;
    int k = idx & 255;
    float v;
    if (which == 0)      v = w_in[k * 256 + n];
    else if (which == 1) v = (n < NOFF) ? w_off[k * NOFF + n]
                           : (n < NOM) ? w_mask[k * NMSK + (n - NOFF)] : 0.f;
    else                 v = w_out[k * 256 + n];
    split1(v, &g_wth[idx], &g_wtl[idx]);
}

// ---------------------------------------------------------------------------
// x (NCHW) -> g_ah/g_al [m][k] via smem transpose.  grid = 784 (32 m per block)
// ---------------------------------------------------------------------------
__global__ __launch_bounds__(256)
void prep_x(const float* __restrict__ x)
{
    __shared__ float s[32][257];
    const int mb = blockIdx.x * 32;
    const int b = mb / 3136, hw0 = mb % 3136;
    const int lane = threadIdx.x & 31, kw = threadIdx.x >> 5;
#pragma unroll
    for (int p = 0; p < 32; p++) {
        int k = p * 8 + kw;
        s[lane][k] = x[((size_t)(b * 256 + k)) * 3136 + hw0 + lane];
    }
    __syncthreads();
    const int row = threadIdx.x >> 3, seg = threadIdx.x & 7;
    const int m = mb + row, k0 = seg * 32;
    uint32_t hi[16], lo[16];
#pragma unroll
    for (int j = 0; j < 16; j++) {
        float a = s[row][k0 + 2 * j], bv = s[row][k0 + 2 * j + 1];
        hi[j] = hi2(a, bv); lo[j] = lo2(a, bv);
    }
    uint4* dh = (uint4*)(g_ah + (size_t)m * 256 + k0);
    uint4* dl = (uint4*)(g_al + (size_t)m * 256 + k0);
#pragma unroll
    for (int q = 0; q < 4; q++) {
        dh[q] = make_uint4(hi[4*q], hi[4*q+1], hi[4*q+2], hi[4*q+3]);
        dl[q] = make_uint4(lo[4*q], lo[4*q+1], lo[4*q+2], lo[4*q+3]);
    }
}

// ---------------------------------------------------------------------------
// Zero only the padding ring of g_vp (interior fully overwritten by gemm<0>).
// ---------------------------------------------------------------------------
__global__ void zero_border_kernel() {
    int cell = blockIdx.x;            // 0..228*8-1
    int b = cell / 228, r = cell % 228;
    int h, w;
    if (r < 58)        { h = 0;  w = r; }
    else if (r < 116)  { h = 57; w = r - 58; }
    else if (r < 172)  { h = r - 116 + 1; w = 0; }
    else               { h = r - 172 + 1; w = 57; }
    g_vp[((size_t)((b * 58 + h) * 58 + w)) * 256 + threadIdx.x] = 0.f;
}

// ---------------------------------------------------------------------------
// Tensor-core GEMM: bf16 3-term split, fp32 accum, cp.async double buffer,
// ldmatrix fragment loads.  Block tile 128m x 64n, 2 CTAs/SM.
// MODE 0: -> g_vp interior (+b_in) | MODE 1: -> g_om | MODE 2: -> out BN+SiLU
// ---------------------------------------------------------------------------
#define SW_BYTES   9216    // 64 rows * 144 B
#define SM_BYTES   18432   // 128 rows * 144 B
#define STG_BYTES  55296   // 2*(SW+SM)
#define SMEM_GEMM  (2 * STG_BYTES)

template<int MODE>
__global__ __launch_bounds__(256, 2)
void gemm_mma(const float* __restrict__ bias,
              const float* __restrict__ bias2,
              float* __restrict__ Cout,
              const float* __restrict__ bn_g, const float* __restrict__ bn_b,
              const float* __restrict__ bn_mean, const float* __restrict__ bn_var)
{
    extern __shared__ char smem[];
    const uint32_t smem_b = smem_u32(smem);

    const int tid = threadIdx.x, wid = tid >> 5, lane = tid & 31;
    const int g = lane >> 2, tig = lane & 3;
    const int mat = lane >> 3, rr = lane & 7;     // ldmatrix lane mapping
    const int nb0 = blockIdx.x * 64, mb0 = blockIdx.y * 128;
    const int nw = wid & 1;     // n-slab (32 W rows)
    const int mw = wid >> 1;    // m-slab (32 act rows)

    const __nv_bfloat16* wth = g_wth + MODE * 65536;
    const __nv_bfloat16* wtl = g_wtl + MODE * 65536;

    float acc[2][4][4];
#pragma unroll
    for (int a = 0; a < 2; a++)
#pragma unroll
        for (int b = 0; b < 4; b++)
#pragma unroll
            for (int c = 0; c < 4; c++) acc[a][b][c] = 0.f;

    auto stage = [&](int buf, int chv) {
        const int k0c = chv * 64;
        const uint32_t base = smem_b + buf * STG_BYTES;
#pragma unroll
        for (int i = 0; i < 2; i++) {              // W: 64 rows, hi+lo
            int idx = i * 256 + tid;
            int r = idx >> 3, seg = idx & 7;
            uint32_t so = base + (uint32_t)(r * 144 + seg * 16);
            size_t wof = (size_t)(nb0 + r) * 256 + k0c + seg * 8;
            cpasync16(so,            wth + wof);
            cpasync16(so + SW_BYTES, wtl + wof);
        }
#pragma unroll
        for (int i = 0; i < 4; i++) {              // M: 128 rows, hi+lo
            int idx = i * 256 + tid;
            int r = idx >> 3, seg = idx & 7;
            uint32_t so = base + 2 * SW_BYTES + (uint32_t)(r * 144 + seg * 16);
            size_t mof = (size_t)(mb0 + r) * 256 + k0c + seg * 8;
            cpasync16(so,            g_ah + mof);
            cpasync16(so + SM_BYTES, g_al + mof);
        }
        CP_COMMIT();
    };

    stage(0, 0);

    for (int chv = 0; chv < 4; chv++) {
        if (chv + 1 < 4) { stage((chv + 1) & 1, chv + 1); CP_WAIT(1); }
        else             { CP_WAIT(0); }
        __syncthreads();

        const uint32_t sbuf = smem_b + (chv & 1) * STG_BYTES;
        const uint32_t sWh = sbuf;
        const uint32_t sWl = sbuf + SW_BYTES;
        const uint32_t sMh = sbuf + 2 * SW_BYTES;
        const uint32_t sMl = sbuf + 2 * SW_BYTES + SM_BYTES;

#pragma unroll
        for (int ks = 0; ks < 4; ks++) {
            const int kb = ks * 32;   // byte offset of 16-k chunk
            uint32_t wh[2][4], wl[2][4], mh[4][2], ml[4][2];

            // W (A-operand) frags: mat&1 -> row block (+8), mat>>1 -> k block (+16B)
#pragma unroll
            for (int mt = 0; mt < 2; mt++) {
                uint32_t off = (uint32_t)((nw * 32 + mt * 16 + rr + (mat & 1) * 8) * 144
                                          + kb + (mat >> 1) * 16);
                ldsm4(wh[mt], sWh + off);
                ldsm4(wl[mt], sWl + off);
            }
            // act (B-operand) frags: mat>>1 -> nt tile (+8 rows), mat&1 -> k block
#pragma unroll
            for (int np = 0; np < 2; np++) {
                uint32_t off = (uint32_t)((mw * 32 + (np * 2 + (mat >> 1)) * 8 + rr) * 144
                                          + kb + (mat & 1) * 16);
                uint32_t t4[4];
                ldsm4(t4, sMh + off);
                mh[np*2][0] = t4[0]; mh[np*2][1] = t4[1];
                mh[np*2+1][0] = t4[2]; mh[np*2+1][1] = t4[3];
                ldsm4(t4, sMl + off);
                ml[np*2][0] = t4[0]; ml[np*2][1] = t4[1];
                ml[np*2+1][0] = t4[2]; ml[np*2+1][1] = t4[3];
            }
#pragma unroll
            for (int mt = 0; mt < 2; mt++)
#pragma unroll
                for (int nt = 0; nt < 4; nt++)
                    mma16816(acc[mt][nt], wh[mt], mh[nt]);
#pragma unroll
            for (int mt = 0; mt < 2; mt++)
#pragma unroll
                for (int nt = 0; nt < 4; nt++)
                    mma16816(acc[mt][nt], wh[mt], ml[nt]);
#pragma unroll
            for (int mt = 0; mt < 2; mt++)
#pragma unroll
                for (int nt = 0; nt < 4; nt++)
                    mma16816(acc[mt][nt], wl[mt], mh[nt]);
        }
        __syncthreads();
    }

    // ---- stage C tile [m_loc][n_loc], stride 65 ----
    float* sOut = (float*)smem;
#pragma unroll
    for (int mt = 0; mt < 2; mt++)
#pragma unroll
        for (int nt = 0; nt < 4; nt++) {
            int n_loc = nw * 32 + mt * 16 + g;
            int m_loc = mw * 32 + nt * 8 + tig * 2;
            sOut[m_loc * 65 + n_loc]           = acc[mt][nt][0];
            sOut[(m_loc + 1) * 65 + n_loc]     = acc[mt][nt][1];
            sOut[m_loc * 65 + n_loc + 8]       = acc[mt][nt][2];
            sOut[(m_loc + 1) * 65 + n_loc + 8] = acc[mt][nt][3];
        }
    __syncthreads();

    // ---- mode-specific global stores ----
    if (MODE == 0) {
        for (int t = tid; t < 128 * 16; t += 256) {
            int m_loc = t >> 4, c4 = (t & 15) * 4;
            int m = mb0 + m_loc;
            int b = m / 3136, hw = m - b * 3136;
            int h = hw / 56, w = hw - h * 56;
            float4 v;
            v.x = sOut[m_loc * 65 + c4 + 0] + __ldg(&bias[nb0 + c4 + 0]);
            v.y = sOut[m_loc * 65 + c4 + 1] + __ldg(&bias[nb0 + c4 + 1]);
            v.z = sOut[m_loc * 65 + c4 + 2] + __ldg(&bias[nb0 + c4 + 2]);
            v.w = sOut[m_loc * 65 + c4 + 3] + __ldg(&bias[nb0 + c4 + 3]);
            *(float4*)(g_vp + ((size_t)((b * 58 + h + 1) * 58 + (w + 1))) * 256
                       + nb0 + c4) = v;
        }
    } else if (MODE == 1) {
        int navail = NOM - nb0; if (navail > 64) navail = 64;
        if (navail > 0) {
            const int nq = navail >> 2;
            for (int t = tid; t < 128 * nq; t += 256) {
                int m_loc = t / nq, c4 = (t - m_loc * nq) * 4;
                int n = nb0 + c4;
                float4 v;
                float* sp = &sOut[m_loc * 65 + c4];
                v.x = sp[0] + ((n + 0 < NOFF) ? __ldg(&bias[n + 0]) : __ldg(&bias2[n + 0 - NOFF]));
                v.y = sp[1] + ((n + 1 < NOFF) ? __ldg(&bias[n + 1]) : __ldg(&bias2[n + 1 - NOFF]));
                v.z = sp[2] + ((n + 2 < NOFF) ? __ldg(&bias[n + 2]) : __ldg(&bias2[n + 2 - NOFF]));
                v.w = sp[3] + ((n + 3 < NOFF) ? __ldg(&bias[n + 3]) : __ldg(&bias2[n + 3 - NOFF]));
                *(float4*)(g_om + (size_t)(mb0 + m_loc) * 216 + n) = v;
            }
        }
    } else {
        for (int ni = wid; ni < 64; ni += 8) {
            int n = nb0 + ni;
            float kA = __ldg(&bn_g[n]) * rsqrtf(__ldg(&bn_var[n]) + 1e-5f);
            float kB = (__ldg(&bias[n]) - __ldg(&bn_mean[n])) * kA + __ldg(&bn_b[n]);
#pragma unroll
            for (int mh2 = 0; mh2 < 4; mh2++) {
                int m_loc = mh2 * 32 + lane;
                int m = mb0 + m_loc;
                int b = m / 3136, hw = m - b * 3136;
                float f = sOut[m_loc * 65 + ni] * kA + kB;
                float o = f / (1.f + expf(-f));
                Cout[((size_t)(b * 256 + n)) * 3136 + hw] = o;
            }
        }
    }
}

// ---------------------------------------------------------------------------
// Depthwise 3x3 conv (NCHW in) -> NHWC g_f (pre-LN).
// ---------------------------------------------------------------------------
__global__ __launch_bounds__(256)
void dwconv_kernel(const float* __restrict__ x,
                   const float* __restrict__ dw_w,
                   const float* __restrict__ dw_b)
{
    __shared__ float sx[32 * 177];
    __shared__ float sw_[32 * 9];
    __shared__ float sb_[32];

    const int c0  = blockIdx.x * 32;
    const int h   = blockIdx.y;
    const int b   = blockIdx.z;
    const int tid = threadIdx.x;

    for (int i = tid; i < 288; i += 256) sw_[i] = dw_w[c0 * 9 + i];
    if (tid < 32) sb_[tid] = dw_b[c0 + tid];

    for (int idx = tid; idx < 32 * 3 * 58; idx += 256) {
        int col = idx % 58;
        int r   = (idx / 58) % 3;
        int c   = idx / 174;
        int hh  = h - 1 + r;
        int wwc = col - 1;
        float v = 0.f;
        if (hh >= 0 && hh < 56 && wwc >= 0 && wwc < 56)
            v = x[((size_t)(b * 256 + c0 + c)) * 3136 + hh * 56 + wwc];
        sx[c * 177 + r * 59 + col] = v;
    }
    __syncthreads();

    for (int oi = tid; oi < 32 * 56; oi += 256) {
        int c = oi & 31;
        int w = oi >> 5;
        float accv = sb_[c];
#pragma unroll
        for (int r = 0; r < 3; r++)
#pragma unroll
            for (int j = 0; j < 3; j++)
                accv = fmaf(sx[c * 177 + r * 59 + w + j], sw_[c * 9 + r * 3 + j], accv);
        g_f[((size_t)((b * 56 + h) * 56 + w)) * 256 + c0 + c] = accv;
    }
}

// ---------------------------------------------------------------------------
// LayerNorm (C=256) + exact GELU; warp-per-position; writes split bf16.
// ---------------------------------------------------------------------------
__global__ __launch_bounds__(256)
void ln_gelu_kernel(const float* __restrict__ ln_g,
                    const float* __restrict__ ln_b)
{
    const int warp = threadIdx.x >> 5, lane = threadIdx.x & 31;
    const int m = blockIdx.x * 8 + warp;
    const int k0 = lane * 8;

    const float* src = g_f + (size_t)m * 256 + k0;
    float4 v0 = *(const float4*)src;
    float4 v1 = *(const float4*)(src + 4);
    float e[8] = {v0.x, v0.y, v0.z, v0.w, v1.x, v1.y, v1.z, v1.w};

    float s = 0.f, s2 = 0.f;
#pragma unroll
    for (int j = 0; j < 8; j++) { s += e[j]; s2 += e[j] * e[j]; }
#pragma unroll
    for (int o = 16; o; o >>= 1) {
        s  += __shfl_xor_sync(0xffffffffu, s,  o);
        s2 += __shfl_xor_sync(0xffffffffu, s2, o);
    }
    float mean = s * (1.f / 256.f);
    float var  = s2 * (1.f / 256.f) - mean * mean;
    float rstd = rsqrtf(var + 1e-5f);

    uint32_t hi[4], lo[4];
#pragma unroll
    for (int j = 0; j < 4; j++) {
        float a = (e[2*j]   - mean) * rstd * __ldg(&ln_g[k0 + 2*j])   + __ldg(&ln_b[k0 + 2*j]);
        float b = (e[2*j+1] - mean) * rstd * __ldg(&ln_g[k0 + 2*j+1]) + __ldg(&ln_b[k0 + 2*j+1]);
        a = 0.5f * a * (1.f + erff(a * 0.70710678118654752f));
        b = 0.5f * b * (1.f + erff(b * 0.70710678118654752f));
        hi[j] = hi2(a, b); lo[j] = lo2(a, b);
    }
    *(uint4*)(g_ah + (size_t)m * 256 + k0) = make_uint4(hi[0], hi[1], hi[2], hi[3]);
    *(uint4*)(g_al + (size_t)m * 256 + k0) = make_uint4(lo[0], lo[1], lo[2], lo[3]);
}

// ---------------------------------------------------------------------------
// Deformable sampling. grid (3136, 8): block = 8 consecutive positions x one
// group -> overlapping bilinear footprints hit in L1.
// ---------------------------------------------------------------------------
__global__ __launch_bounds__(256)
void sample_kernel()
{
    const int wi   = threadIdx.x >> 5;
    const int lane = threadIdx.x & 31;
    const int m    = blockIdx.x * 8 + wi;
    const int g    = blockIdx.y;

    const int b    = m / 3136;
    const int hw   = m - b * 3136;
    const int h    = hw / 56;
    const int w    = hw - h * 56;

    const float* row = g_om + (size_t)m * 216;

    float offx[9], offy[9], mk[9];
    float mx = -3.0e38f;
#pragma unroll
    for (int p = 0; p < 9; p++) {
        offx[p] = row[g * 18 + 2 * p];
        offy[p] = row[g * 18 + 2 * p + 1];
        mk[p]   = row[144 + g * 9 + p];
        mx = fmaxf(mx, mk[p]);
    }
    float sum = 0.f;
#pragma unroll
    for (int p = 0; p < 9; p++) { mk[p] = expf(mk[p] - mx); sum += mk[p]; }
    const float inv = 1.f / sum;

    float acc = 0.f;
    const float* vpg = g_vp + (size_t)b * 58 * 58 * 256 + g * 32 + lane;

#pragma unroll
    for (int p = 0; p < 9; p++) {
        float px = (float)(w + (p / 3)) + offx[p];
        float py = (float)(h + (p % 3)) + offy[p];
        float x0f = floorf(px), y0f = floorf(py);
        float wx = px - x0f, wy = py - y0f;
        int x0 = (int)x0f, y0 = (int)y0f;
        int x1 = x0 + 1,   y1 = y0 + 1;
        float vx0 = (x0 >= 0 && x0 < 58) ? 1.f : 0.f;
        float vx1 = (x1 >= 0 && x1 < 58) ? 1.f : 0.f;
        float vy0 = (y0 >= 0 && y0 < 58) ? 1.f : 0.f;
        float vy1 = (y1 >= 0 && y1 < 58) ? 1.f : 0.f;
        int x0c = min(max(x0, 0), 57), x1c = min(max(x1, 0), 57);
        int y0c = min(max(y0, 0), 57), y1c = min(max(y1, 0), 57);

        float mp  = mk[p] * inv;
        float w00 = (1.f - wx) * (1.f - wy) * vx0 * vy0 * mp;
        float w01 = wx * (1.f - wy) * vx1 * vy0 * mp;
        float w10 = (1.f - wx) * wy * vx0 * vy1 * mp;
        float w11 = wx * wy * vx1 * vy1 * mp;

        acc += w00 * vpg[(y0c * 58 + x0c) * 256]
             + w01 * vpg[(y0c * 58 + x1c) * 256]
             + w10 * vpg[(y1c * 58 + x0c) * 256]
             + w11 * vpg[(y1c * 58 + x1c) * 256];
    }
    int c = g * 32 + lane;
    split1(acc, &g_ah[(size_t)m * 256 + c], &g_al[(size_t)m * 256 + c]);
}

// ---------------------------------------------------------------------------
extern "C" void kernel_launch(void* const* d_in, const int* in_sizes, int n_in,
                              void* d_out, int out_size)
{
    const float* x      = (const float*)d_in[0];
    const float* b_in   = (const float*)d_in[2];
    const float* dw_w   = (const float*)d_in[3];
    const float* dw_b   = (const float*)d_in[4];
    const float* ln_g   = (const float*)d_in[5];
    const float* ln_b   = (const float*)d_in[6];
    const float* b_off  = (const float*)d_in[8];
    const float* b_mask = (const float*)d_in[10];
    const float* b_out  = (const float*)d_in[12];
    const float* bn_g   = (const float*)d_in[13];
    const float* bn_b   = (const float*)d_in[14];
    const float* bn_mean= (const float*)d_in[15];
    const float* bn_var = (const float*)d_in[16];
    float* out = (float*)d_out;

    cudaFuncSetAttribute(gemm_mma<0>, cudaFuncAttributeMaxDynamicSharedMemorySize, SMEM_GEMM);
    cudaFuncSetAttribute(gemm_mma<1>, cudaFuncAttributeMaxDynamicSharedMemorySize, SMEM_GEMM);
    cudaFuncSetAttribute(gemm_mma<2>, cudaFuncAttributeMaxDynamicSharedMemorySize, SMEM_GEMM);

    dim3 ggrid(4, 196);

    prep_weights<<<768, 256>>>((const float*)d_in[1], (const float*)d_in[7],
                               (const float*)d_in[9], (const float*)d_in[11]);
    prep_x<<<784, 256>>>(x);
    zero_border_kernel<<<228 * 8, 256>>>();
    // input projection -> padded vp (NHWC)
    gemm_mma<0><<<ggrid, 256, SMEM_GEMM>>>(b_in, nullptr, nullptr,
                                           nullptr, nullptr, nullptr, nullptr);
    // offset/mask branch
    dwconv_kernel<<<dim3(8, 56, 8), 256>>>(x, dw_w, dw_b);
    ln_gelu_kernel<<<3136, 256>>>(ln_g, ln_b);
    gemm_mma<1><<<ggrid, 256, SMEM_GEMM>>>(b_off, b_mask, nullptr,
                                           nullptr, nullptr, nullptr, nullptr);
    // deformable bilinear sampling + mask aggregation
    sample_kernel<<<dim3(3136, 8), 256>>>();
    // output projection + BN + SiLU -> NCHW
    gemm_mma<2><<<ggrid, 256, SMEM_GEMM>>>(b_out, nullptr, out,
                                           bn_g, bn_b, bn_mean, bn_var);
}

// round 8
// speedup vs baseline: 1.5040x; 1.0210x over previous
#include <cuda_runtime.h>
#include <cuda_bf16.h>
#include <math.h>
#include <stdint.h>

// Problem constants
#define BB    8
#define CC    256
#define HH    56
#define WW    56
#define HIN   58
#define WIN   58
#define MTOT  25088      // B*H*W
#define NOFF  144
#define NMSK  72
#define NOM   216

// Scratch (device globals; no runtime allocation allowed)
__device__ float g_vp[BB*HIN*WIN*CC];        // padded projected features, NHWC fp32
__device__ float g_f [MTOT*CC];              // dwconv output (pre-LN), NHWC fp32
__device__ float g_om[MTOT*NOM];             // [offset(144) | mask(72)] logits
__device__ __nv_bfloat16 g_ah[MTOT*CC];      // activation bf16 hi   [m][k]
__device__ __nv_bfloat16 g_al[MTOT*CC];      // activation bf16 lo   [m][k]
__device__ __nv_bfloat16 g_wth[3*65536];     // weights^T [which][n][k], hi
__device__ __nv_bfloat16 g_wtl[3*65536];     // weights^T lo

// ---------------------------------------------------------------------------
// fp32 -> bf16 hi/lo split helpers
// ---------------------------------------------------------------------------
__device__ __forceinline__ uint32_t hibits(float v) {
    uint32_t u = __float_as_uint(v);
    return (u + 0x7FFFu + ((u >> 16) & 1u)) & 0xFFFF0000u;
}
__device__ __forceinline__ uint32_t hi2(float a, float b) {
    return (hibits(a) >> 16) | (hibits(b) & 0xFFFF0000u);
}
__device__ __forceinline__ uint32_t lo2(float a, float b) {
    float la = a - __uint_as_float(hibits(a));
    float lb = b - __uint_as_float(hibits(b));
    uint32_t r;
    asm("cvt.rn.satfinite.bf16x2.f32 %0, %1, %2;" : "=r"(r) : "f"(lb), "f"(la));
    return r;
}
__device__ __forceinline__ void split1(float v, __nv_bfloat16* ph, __nv_bfloat16* pl) {
    uint32_t hb = hibits(v);
    __nv_bfloat16_raw hr; hr.x = (unsigned short)(hb >> 16);
    *ph = __nv_bfloat16(hr);
    *pl = __float2bfloat16(v - __uint_as_float(hb));
}

// mma.sync m16n8k16 bf16 -> f32 (portable tensor-core path)
__device__ __forceinline__ void mma16816(float* c, const uint32_t* a, const uint32_t* b) {
    asm volatile(
        "mma.sync.aligned.m16n8k16.row.col.f32.bf16.bf16.f32 "
        "{%0,%1,%2,%3}, {%4,%5,%6,%7}, {%8,%9}, {%0,%1,%2,%3};"
        : "+f"(c[0]), "+f"(c[1]), "+f"(c[2]), "+f"(c[3])
        : "r"(a[0]), "r"(a[1]), "r"(a[2]), "r"(a[3]), "r"(b[0]), "r"(b[1]));
}

// ldmatrix x4
__device__ __forceinline__ void ldsm4(uint32_t* r, uint32_t a) {
    asm volatile("ldmatrix.sync.aligned.m8n8.x4.shared.b16 {%0,%1,%2,%3}, [%4];"
        : "=r"(r[0]), "=r"(r[1]), "=r"(r[2]), "=r"(r[3]) : "r"(a));
}

__device__ __forceinline__ uint32_t smem_u32(const void* p) {
    uint32_t a;
    asm("{ .reg .u64 t; cvta.to.shared.u64 t, %1; cvt.u32.u64 %0, t; }"
        : "=r"(a) : "l"(p));
    return a;
}
__device__ __forceinline__ void cpasync16(uint32_t dst, const void* src) {
    asm volatile("cp.async.cg.shared.global [%0], [%1], 16;" :: "r"(dst), "l"(src));
}
#define CP_COMMIT()  asm volatile("cp.async.commit_group;" ::: "memory")
#define CP_WAIT(n)   asm volatile("cp.async.wait_group %0;" :: "n"(n) : "memory")

// ---------------------------------------------------------------------------
// Weight prep: transpose + bf16 hi/lo split.
// ---------------------------------------------------------------------------
__global__ void prep_weights(const float* __restrict__ w_in,
                             const float* __restrict__ w_off,
                             const float* __restrict__ w_mask,
                             const float* __restrict__ w_out)
{
    int idx = blockIdx.x * 256 + threadIdx.x;
    int which = idx >> 16;
    int n = (idx >> 8) & 255;
    int k = idx & 255;
    float v;
    if (which == 0)      v = w_in[k * 256 + n];
    else if (which == 1) v = (n < NOFF) ? w_off[k * NOFF + n]
                           : (n < NOM) ? w_mask[k * NMSK + (n - NOFF)] : 0.f;
    else                 v = w_out[k * 256 + n];
    split1(v, &g_wth[idx], &g_wtl[idx]);
}

// ---------------------------------------------------------------------------
// x (NCHW) -> g_ah/g_al [m][k] via smem transpose.  grid = 784
// ---------------------------------------------------------------------------
__global__ __launch_bounds__(256)
void prep_x(const float* __restrict__ x)
{
    __shared__ float s[32][257];
    const int mb = blockIdx.x * 32;
    const int b = mb / 3136, hw0 = mb % 3136;
    const int lane = threadIdx.x & 31, kw = threadIdx.x >> 5;
#pragma unroll
    for (int p = 0; p < 32; p++) {
        int k = p * 8 + kw;
        s[lane][k] = x[((size_t)(b * 256 + k)) * 3136 + hw0 + lane];
    }
    __syncthreads();
    const int row = threadIdx.x >> 3, seg = threadIdx.x & 7;
    const int m = mb + row, k0 = seg * 32;
    uint32_t hi[16], lo[16];
#pragma unroll
    for (int j = 0; j < 16; j++) {
        float a = s[row][k0 + 2 * j], bv = s[row][k0 + 2 * j + 1];
        hi[j] = hi2(a, bv); lo[j] = lo2(a, bv);
    }
    uint4* dh = (uint4*)(g_ah + (size_t)m * 256 + k0);
    uint4* dl = (uint4*)(g_al + (size_t)m * 256 + k0);
#pragma unroll
    for (int q = 0; q < 4; q++) {
        dh[q] = make_uint4(hi[4*q], hi[4*q+1], hi[4*q+2], hi[4*q+3]);
        dl[q] = make_uint4(lo[4*q], lo[4*q+1], lo[4*q+2], lo[4*q+3]);
    }
}

// ---------------------------------------------------------------------------
// Zero only the padding ring of g_vp.
// ---------------------------------------------------------------------------
__global__ void zero_border_kernel() {
    int cell = blockIdx.x;            // 0..228*8-1
    int b = cell / 228, r = cell % 228;
    int h, w;
    if (r < 58)        { h = 0;  w = r; }
    else if (r < 116)  { h = 57; w = r - 58; }
    else if (r < 172)  { h = r - 116 + 1; w = 0; }
    else               { h = r - 172 + 1; w = 57; }
    g_vp[((size_t)((b * 58 + h) * 58 + w)) * 256 + threadIdx.x] = 0.f;
}

// ---------------------------------------------------------------------------
// Tensor-core GEMM (unchanged from R7 — at the HMMA fallback roofline).
// ---------------------------------------------------------------------------
#define SW_BYTES   9216    // 64 rows * 144 B
#define SM_BYTES   18432   // 128 rows * 144 B
#define STG_BYTES  55296   // 2*(SW+SM)
#define SMEM_GEMM  (2 * STG_BYTES)

template<int MODE>
__global__ __launch_bounds__(256, 2)
void gemm_mma(const float* __restrict__ bias,
              const float* __restrict__ bias2,
              float* __restrict__ Cout,
              const float* __restrict__ bn_g, const float* __restrict__ bn_b,
              const float* __restrict__ bn_mean, const float* __restrict__ bn_var)
{
    extern __shared__ char smem[];
    const uint32_t smem_b = smem_u32(smem);

    const int tid = threadIdx.x, wid = tid >> 5, lane = tid & 31;
    const int g = lane >> 2, tig = lane & 3;
    const int mat = lane >> 3, rr = lane & 7;
    const int nb0 = blockIdx.x * 64, mb0 = blockIdx.y * 128;
    const int nw = wid & 1;
    const int mw = wid >> 1;

    const __nv_bfloat16* wth = g_wth + MODE * 65536;
    const __nv_bfloat16* wtl = g_wtl + MODE * 65536;

    float acc[2][4][4];
#pragma unroll
    for (int a = 0; a < 2; a++)
#pragma unroll
        for (int b = 0; b < 4; b++)
#pragma unroll
            for (int c = 0; c < 4; c++) acc[a][b][c] = 0.f;

    auto stage = [&](int buf, int chv) {
        const int k0c = chv * 64;
        const uint32_t base = smem_b + buf * STG_BYTES;
#pragma unroll
        for (int i = 0; i < 2; i++) {
            int idx = i * 256 + tid;
            int r = idx >> 3, seg = idx & 7;
            uint32_t so = base + (uint32_t)(r * 144 + seg * 16);
            size_t wof = (size_t)(nb0 + r) * 256 + k0c + seg * 8;
            cpasync16(so,            wth + wof);
            cpasync16(so + SW_BYTES, wtl + wof);
        }
#pragma unroll
        for (int i = 0; i < 4; i++) {
            int idx = i * 256 + tid;
            int r = idx >> 3, seg = idx & 7;
            uint32_t so = base + 2 * SW_BYTES + (uint32_t)(r * 144 + seg * 16);
            size_t mof = (size_t)(mb0 + r) * 256 + k0c + seg * 8;
            cpasync16(so,            g_ah + mof);
            cpasync16(so + SM_BYTES, g_al + mof);
        }
        CP_COMMIT();
    };

    stage(0, 0);

    for (int chv = 0; chv < 4; chv++) {
        if (chv + 1 < 4) { stage((chv + 1) & 1, chv + 1); CP_WAIT(1); }
        else             { CP_WAIT(0); }
        __syncthreads();

        const uint32_t sbuf = smem_b + (chv & 1) * STG_BYTES;
        const uint32_t sWh = sbuf;
        const uint32_t sWl = sbuf + SW_BYTES;
        const uint32_t sMh = sbuf + 2 * SW_BYTES;
        const uint32_t sMl = sbuf + 2 * SW_BYTES + SM_BYTES;

#pragma unroll
        for (int ks = 0; ks < 4; ks++) {
            const int kb = ks * 32;
            uint32_t wh[2][4], wl[2][4], mh[4][2], ml[4][2];
#pragma unroll
            for (int mt = 0; mt < 2; mt++) {
                uint32_t off = (uint32_t)((nw * 32 + mt * 16 + rr + (mat & 1) * 8) * 144
                                          + kb + (mat >> 1) * 16);
                ldsm4(wh[mt], sWh + off);
                ldsm4(wl[mt], sWl + off);
            }
#pragma unroll
            for (int np = 0; np < 2; np++) {
                uint32_t off = (uint32_t)((mw * 32 + (np * 2 + (mat >> 1)) * 8 + rr) * 144
                                          + kb + (mat & 1) * 16);
                uint32_t t4[4];
                ldsm4(t4, sMh + off);
                mh[np*2][0] = t4[0]; mh[np*2][1] = t4[1];
                mh[np*2+1][0] = t4[2]; mh[np*2+1][1] = t4[3];
                ldsm4(t4, sMl + off);
                ml[np*2][0] = t4[0]; ml[np*2][1] = t4[1];
                ml[np*2+1][0] = t4[2]; ml[np*2+1][1] = t4[3];
            }
#pragma unroll
            for (int mt = 0; mt < 2; mt++)
#pragma unroll
                for (int nt = 0; nt < 4; nt++)
                    mma16816(acc[mt][nt], wh[mt], mh[nt]);
#pragma unroll
            for (int mt = 0; mt < 2; mt++)
#pragma unroll
                for (int nt = 0; nt < 4; nt++)
                    mma16816(acc[mt][nt], wh[mt], ml[nt]);
#pragma unroll
            for (int mt = 0; mt < 2; mt++)
#pragma unroll
                for (int nt = 0; nt < 4; nt++)
                    mma16816(acc[mt][nt], wl[mt], mh[nt]);
        }
        __syncthreads();
    }

    float* sOut = (float*)smem;
#pragma unroll
    for (int mt = 0; mt < 2; mt++)
#pragma unroll
        for (int nt = 0; nt < 4; nt++) {
            int n_loc = nw * 32 + mt * 16 + g;
            int m_loc = mw * 32 + nt * 8 + tig * 2;
            sOut[m_loc * 65 + n_loc]           = acc[mt][nt][0];
            sOut[(m_loc + 1) * 65 + n_loc]     = acc[mt][nt][1];
            sOut[m_loc * 65 + n_loc + 8]       = acc[mt][nt][2];
            sOut[(m_loc + 1) * 65 + n_loc + 8] = acc[mt][nt][3];
        }
    __syncthreads();

    if (MODE == 0) {
        for (int t = tid; t < 128 * 16; t += 256) {
            int m_loc = t >> 4, c4 = (t & 15) * 4;
            int m = mb0 + m_loc;
            int b = m / 3136, hw = m - b * 3136;
            int h = hw / 56, w = hw - h * 56;
            float4 v;
            v.x = sOut[m_loc * 65 + c4 + 0] + __ldg(&bias[nb0 + c4 + 0]);
            v.y = sOut[m_loc * 65 + c4 + 1] + __ldg(&bias[nb0 + c4 + 1]);
            v.z = sOut[m_loc * 65 + c4 + 2] + __ldg(&bias[nb0 + c4 + 2]);
            v.w = sOut[m_loc * 65 + c4 + 3] + __ldg(&bias[nb0 + c4 + 3]);
            *(float4*)(g_vp + ((size_t)((b * 58 + h + 1) * 58 + (w + 1))) * 256
                       + nb0 + c4) = v;
        }
    } else if (MODE == 1) {
        int navail = NOM - nb0; if (navail > 64) navail = 64;
        if (navail > 0) {
            const int nq = navail >> 2;
            for (int t = tid; t < 128 * nq; t += 256) {
                int m_loc = t / nq, c4 = (t - m_loc * nq) * 4;
                int n = nb0 + c4;
                float4 v;
                float* sp = &sOut[m_loc * 65 + c4];
                v.x = sp[0] + ((n + 0 < NOFF) ? __ldg(&bias[n + 0]) : __ldg(&bias2[n + 0 - NOFF]));
                v.y = sp[1] + ((n + 1 < NOFF) ? __ldg(&bias[n + 1]) : __ldg(&bias2[n + 1 - NOFF]));
                v.z = sp[2] + ((n + 2 < NOFF) ? __ldg(&bias[n + 2]) : __ldg(&bias2[n + 2 - NOFF]));
                v.w = sp[3] + ((n + 3 < NOFF) ? __ldg(&bias[n + 3]) : __ldg(&bias2[n + 3 - NOFF]));
                *(float4*)(g_om + (size_t)(mb0 + m_loc) * 216 + n) = v;
            }
        }
    } else {
        for (int ni = wid; ni < 64; ni += 8) {
            int n = nb0 + ni;
            float kA = __ldg(&bn_g[n]) * rsqrtf(__ldg(&bn_var[n]) + 1e-5f);
            float kB = (__ldg(&bias[n]) - __ldg(&bn_mean[n])) * kA + __ldg(&bn_b[n]);
#pragma unroll
            for (int mh2 = 0; mh2 < 4; mh2++) {
                int m_loc = mh2 * 32 + lane;
                int m = mb0 + m_loc;
                int b = m / 3136, hw = m - b * 3136;
                float f = sOut[m_loc * 65 + ni] * kA + kB;
                float o = f / (1.f + expf(-f));
                Cout[((size_t)(b * 256 + n)) * 3136 + hw] = o;
            }
        }
    }
}

// ---------------------------------------------------------------------------
// Depthwise 3x3 conv (NCHW in) -> NHWC g_f (pre-LN).
// ---------------------------------------------------------------------------
__global__ __launch_bounds__(256)
void dwconv_kernel(const float* __restrict__ x,
                   const float* __restrict__ dw_w,
                   const float* __restrict__ dw_b)
{
    __shared__ float sx[32 * 177];
    __shared__ float sw_[32 * 9];
    __shared__ float sb_[32];

    const int c0  = blockIdx.x * 32;
    const int h   = blockIdx.y;
    const int b   = blockIdx.z;
    const int tid = threadIdx.x;

    for (int i = tid; i < 288; i += 256) sw_[i] = dw_w[c0 * 9 + i];
    if (tid < 32) sb_[tid] = dw_b[c0 + tid];

    for (int idx = tid; idx < 32 * 3 * 58; idx += 256) {
        int col = idx % 58;
        int r   = (idx / 58) % 3;
        int c   = idx / 174;
        int hh  = h - 1 + r;
        int wwc = col - 1;
        float v = 0.f;
        if (hh >= 0 && hh < 56 && wwc >= 0 && wwc < 56)
            v = x[((size_t)(b * 256 + c0 + c)) * 3136 + hh * 56 + wwc];
        sx[c * 177 + r * 59 + col] = v;
    }
    __syncthreads();

    for (int oi = tid; oi < 32 * 56; oi += 256) {
        int c = oi & 31;
        int w = oi >> 5;
        float accv = sb_[c];
#pragma unroll
        for (int r = 0; r < 3; r++)
#pragma unroll
            for (int j = 0; j < 3; j++)
                accv = fmaf(sx[c * 177 + r * 59 + w + j], sw_[c * 9 + r * 3 + j], accv);
        g_f[((size_t)((b * 56 + h) * 56 + w)) * 256 + c0 + c] = accv;
    }
}

// ---------------------------------------------------------------------------
// LayerNorm (C=256) + exact GELU; warp-per-position; writes split bf16.
// ---------------------------------------------------------------------------
__global__ __launch_bounds__(256)
void ln_gelu_kernel(const float* __restrict__ ln_g,
                    const float* __restrict__ ln_b)
{
    const int warp = threadIdx.x >> 5, lane = threadIdx.x & 31;
    const int m = blockIdx.x * 8 + warp;
    const int k0 = lane * 8;

    const float* src = g_f + (size_t)m * 256 + k0;
    float4 v0 = *(const float4*)src;
    float4 v1 = *(const float4*)(src + 4);
    float e[8] = {v0.x, v0.y, v0.z, v0.w, v1.x, v1.y, v1.z, v1.w};

    float s = 0.f, s2 = 0.f;
#pragma unroll
    for (int j = 0; j < 8; j++) { s += e[j]; s2 += e[j] * e[j]; }
#pragma unroll
    for (int o = 16; o; o >>= 1) {
        s  += __shfl_xor_sync(0xffffffffu, s,  o);
        s2 += __shfl_xor_sync(0xffffffffu, s2, o);
    }
    float mean = s * (1.f / 256.f);
    float var  = s2 * (1.f / 256.f) - mean * mean;
    float rstd = rsqrtf(var + 1e-5f);

    uint32_t hi[4], lo[4];
#pragma unroll
    for (int j = 0; j < 4; j++) {
        float a = (e[2*j]   - mean) * rstd * __ldg(&ln_g[k0 + 2*j])   + __ldg(&ln_b[k0 + 2*j]);
        float b = (e[2*j+1] - mean) * rstd * __ldg(&ln_g[k0 + 2*j+1]) + __ldg(&ln_b[k0 + 2*j+1]);
        a = 0.5f * a * (1.f + erff(a * 0.70710678118654752f));
        b = 0.5f * b * (1.f + erff(b * 0.70710678118654752f));
        hi[j] = hi2(a, b); lo[j] = lo2(a, b);
    }
    *(uint4*)(g_ah + (size_t)m * 256 + k0) = make_uint4(hi[0], hi[1], hi[2], hi[3]);
    *(uint4*)(g_al + (size_t)m * 256 + k0) = make_uint4(lo[0], lo[1], lo[2], lo[3]);
}

// ---------------------------------------------------------------------------
// Deformable sampling, float4-vectorized gathers.
// grid (3136, 8): block = 8 consecutive positions x one group.
// Warp layout: qid = lane>>3 handles bilinear corner qid for all 9 taps;
// lane ql = lane&7 covers channels ql*4..ql*4+3 (one float4 per gather).
// 9 LDG.128 per warp instead of 36 LDG.32.  Cross-corner sum via shfl.
// ---------------------------------------------------------------------------
__global__ __launch_bounds__(256)
void sample_kernel()
{
    const int wi   = threadIdx.x >> 5;
    const int lane = threadIdx.x & 31;
    const int qid  = lane >> 3;       // corner 0..3
    const int ql   = lane & 7;        // channel quad 0..7
    const int m    = blockIdx.x * 8 + wi;
    const int g    = blockIdx.y;

    const int b    = m / 3136;
    const int hw   = m - b * 3136;
    const int h    = hw / 56;
    const int w    = hw - h * 56;

    const float* row = g_om + (size_t)m * 216;

    float offx[9], offy[9], mk[9];
    float mx = -3.0e38f;
#pragma unroll
    for (int p = 0; p < 9; p++) {
        offx[p] = row[g * 18 + 2 * p];
        offy[p] = row[g * 18 + 2 * p + 1];
        mk[p]   = row[144 + g * 9 + p];
        mx = fmaxf(mx, mk[p]);
    }
    float sum = 0.f;
#pragma unroll
    for (int p = 0; p < 9; p++) { mk[p] = expf(mk[p] - mx); sum += mk[p]; }
    const float inv = 1.f / sum;

    // per-lane base: batch image + group + channel quad
    const float* vpg = g_vp + (size_t)b * 58 * 58 * 256 + g * 32 + ql * 4;

    float4 acc = make_float4(0.f, 0.f, 0.f, 0.f);

#pragma unroll
    for (int p = 0; p < 9; p++) {
        float px = (float)(w + (p / 3)) + offx[p];
        float py = (float)(h + (p % 3)) + offy[p];
        float x0f = floorf(px), y0f = floorf(py);
        float wx = px - x0f, wy = py - y0f;
        int x0 = (int)x0f, y0 = (int)y0f;
        int x1 = x0 + 1,   y1 = y0 + 1;
        float vx0 = (x0 >= 0 && x0 < 58) ? 1.f : 0.f;
        float vx1 = (x1 >= 0 && x1 < 58) ? 1.f : 0.f;
        float vy0 = (y0 >= 0 && y0 < 58) ? 1.f : 0.f;
        float vy1 = (y1 >= 0 && y1 < 58) ? 1.f : 0.f;
        int x0c = min(max(x0, 0), 57), x1c = min(max(x1, 0), 57);
        int y0c = min(max(y0, 0), 57), y1c = min(max(y1, 0), 57);

        const float mp = mk[p] * inv;
        // this quarter's corner
        float wgt; int yy, xx;
        if (qid == 0)      { wgt = (1.f - wx) * (1.f - wy) * vx0 * vy0; yy = y0c; xx = x0c; }
        else if (qid == 1) { wgt = wx * (1.f - wy) * vx1 * vy0;         yy = y0c; xx = x1c; }
        else if (qid == 2) { wgt = (1.f - wx) * wy * vx0 * vy1;         yy = y1c; xx = x0c; }
        else               { wgt = wx * wy * vx1 * vy1;                 yy = y1c; xx = x1c; }
        wgt *= mp;

        float4 v = *(const float4*)(vpg + (size_t)(yy * 58 + xx) * 256);
        acc.x = fmaf(wgt, v.x, acc.x);
        acc.y = fmaf(wgt, v.y, acc.y);
        acc.z = fmaf(wgt, v.z, acc.z);
        acc.w = fmaf(wgt, v.w, acc.w);
    }

    // sum the 4 corners (lanes ql, ql+8, ql+16, ql+24)
#pragma unroll
    for (int o = 8; o <= 16; o <<= 1) {
        acc.x += __shfl_xor_sync(0xffffffffu, acc.x, o);
        acc.y += __shfl_xor_sync(0xffffffffu, acc.y, o);
        acc.z += __shfl_xor_sync(0xffffffffu, acc.z, o);
        acc.w += __shfl_xor_sync(0xffffffffu, acc.w, o);
    }

    if (qid == 0) {
        int c = g * 32 + ql * 4;
        uint2 hv, lv;
        hv.x = hi2(acc.x, acc.y); hv.y = hi2(acc.z, acc.w);
        lv.x = lo2(acc.x, acc.y); lv.y = lo2(acc.z, acc.w);
        *(uint2*)(g_ah + (size_t)m * 256 + c) = hv;
        *(uint2*)(g_al + (size_t)m * 256 + c) = lv;
    }
}

// ---------------------------------------------------------------------------
extern "C" void kernel_launch(void* const* d_in, const int* in_sizes, int n_in,
                              void* d_out, int out_size)
{
    const float* x      = (const float*)d_in[0];
    const float* b_in   = (const float*)d_in[2];
    const float* dw_w   = (const float*)d_in[3];
    const float* dw_b   = (const float*)d_in[4];
    const float* ln_g   = (const float*)d_in[5];
    const float* ln_b   = (const float*)d_in[6];
    const float* b_off  = (const float*)d_in[8];
    const float* b_mask = (const float*)d_in[10];
    const float* b_out  = (const float*)d_in[12];
    const float* bn_g   = (const float*)d_in[13];
    const float* bn_b   = (const float*)d_in[14];
    const float* bn_mean= (const float*)d_in[15];
    const float* bn_var = (const float*)d_in[16];
    float* out = (float*)d_out;

    cudaFuncSetAttribute(gemm_mma<0>, cudaFuncAttributeMaxDynamicSharedMemorySize, SMEM_GEMM);
    cudaFuncSetAttribute(gemm_mma<1>, cudaFuncAttributeMaxDynamicSharedMemorySize, SMEM_GEMM);
    cudaFuncSetAttribute(gemm_mma<2>, cudaFuncAttributeMaxDynamicSharedMemorySize, SMEM_GEMM);

    dim3 ggrid(4, 196);

    prep_weights<<<768, 256>>>((const float*)d_in[1], (const float*)d_in[7],
                               (const float*)d_in[9], (const float*)d_in[11]);
    prep_x<<<784, 256>>>(x);
    zero_border_kernel<<<228 * 8, 256>>>();
    // input projection -> padded vp (NHWC)
    gemm_mma<0><<<ggrid, 256, SMEM_GEMM>>>(b_in, nullptr, nullptr,
                                           nullptr, nullptr, nullptr, nullptr);
    // offset/mask branch
    dwconv_kernel<<<dim3(8, 56, 8), 256>>>(x, dw_w, dw_b);
    ln_gelu_kernel<<<3136, 256>>>(ln_g, ln_b);
    gemm_mma<1><<<ggrid, 256, SMEM_GEMM>>>(b_off, b_mask, nullptr,
                                           nullptr, nullptr, nullptr, nullptr);
    // deformable bilinear sampling + mask aggregation
    sample_kernel<<<dim3(3136, 8), 256>>>();
    // output projection + BN + SiLU -> NCHW
    gemm_mma<2><<<ggrid, 256, SMEM_GEMM>>>(b_out, nullptr, out,
                                           bn_g, bn_b, bn_mean, bn_var);
}